// round 15
// baseline (speedup 1.0000x reference)
#include <cuda_runtime.h>
#include <cuda_bf16.h>
#include <cstdint>
#include <math.h>

// ---------------- problem constants ----------------
#define PB   4
#define PN1  2048
#define PN2  512
#define PD   768
#define PH   8
#define PDK  64
#define PDV  96
#define PNRP 96
#define PDY0 1536
#define PDFF 1536
#define PMQ  2560
#define PSCALE 0.125f
#define HDK  512
#define HDV  768
#define NQV  1280              // HDK + HDV merged projection width

// ---------------- fp32 scratch ----------------
#define OFF_Y      0L
#define OFF_QV     (OFF_Y    + (long)PB*PN2*PD)
#define OFF_KV     (OFF_QV   + (long)PB*PN1*NQV)
#define OFF_REL    (OFF_KV   + (long)PB*PN2*NQV)
#define OFF_ATT    (OFF_REL  + (long)PB*PH*PN2*PMQ)
#define OFF_X4     (OFF_ATT  + (long)PB*PH*PN1*PN2)
#define OFF_Y4     (OFF_X4   + (long)PB*PN1*PD)
#define SCRATCH_TOTAL (OFF_Y4 + (long)PB*PN2*PD)
__device__ float g_scratch[SCRATCH_TOTAL];

// ---------------- bf16 plane scratch ----------------
#define SZ_X1   ((long)PB*PN1*PD)
#define SZ_Y1   ((long)PB*PN2*PD)
#define SZ_Y0   ((long)PB*PN2*PDY0)
#define SZ_QV1  ((long)PB*PN1*NQV)
#define SZ_KV2  ((long)PB*PN2*NQV)
#define SZ_KB   ((long)PB*PN2*HDK)
#define SZ_RQ   ((long)PMQ*HDK)
#define SZ_ATT  ((long)PB*PH*PN1*PN2)
#define SZ_ATTT ((long)PB*PH*PN1*PN2)
#define SZ_V2T  ((long)PB*PH*PDV*PN2)
#define SZ_V1T  ((long)PB*PH*PDV*PN1)
#define SZ_GO1  ((long)PB*PN1*HDV)
#define SZ_GO2  ((long)PB*PN2*HDV)
#define SZ_GH   ((long)PB*PN1*PDFF)
#define SZ_POS  ((long)PMQ*PNRP)
#define SZ_WRT  ((long)PDY0*PD)
#define SZ_WQV1 ((long)NQV*PD)
#define SZ_WKV2 ((long)NQV*PD)
#define SZ_WO1T ((long)HDV*PD)
#define SZ_WO2T ((long)HDV*PD)
#define SZ_WRELT ((long)HDK*PNRP)
#define SZ_F1   ((long)PD*PDFF)
#define SZ_F2   ((long)PDFF*PD)

#define BF_X1   0L
#define BF_Y1   (BF_X1   + 2*SZ_X1)
#define BF_Y0   (BF_Y1   + 2*SZ_Y1)
#define BF_QP   (BF_Y0   + 2*SZ_Y0)      // merged q|v1 planes [M, 1280] h then l
#define BF_KP   (BF_QP   + 2*SZ_QV1)     // merged k|v2 planes
#define BF_KB   (BF_KP   + 2*SZ_KV2)     // hi+lo (restored)
#define BF_RQ   (BF_KB   + 2*SZ_KB)
#define BF_ATT  (BF_RQ   + 2*SZ_RQ)      // single plane
#define BF_ATTT (BF_ATT  + SZ_ATT)       // single plane
#define BF_V2T  (BF_ATTT + SZ_ATTT)
#define BF_V1T  (BF_V2T  + 2*SZ_V2T)
#define BF_GO1  (BF_V1T  + 2*SZ_V1T)     // hi+lo (restored)
#define BF_GO2  (BF_GO1  + 2*SZ_GO1)     // hi+lo (restored)
#define BF_GH   (BF_GO2  + 2*SZ_GO2)     // single plane
#define BF_POS  (BF_GH   + SZ_GH)
#define BF_WRT  (BF_POS  + 2*SZ_POS)
#define BF_WQV1 (BF_WRT  + 2*SZ_WRT)     // h plane [1280*768], then l plane
#define BF_WKV2 (BF_WQV1 + 2*SZ_WQV1)
#define BF_WO1T (BF_WKV2 + 2*SZ_WKV2)
#define BF_WO2T (BF_WO1T + 2*SZ_WO1T)
#define BF_WRELT (BF_WO2T+ 2*SZ_WO2T)
#define BF_FX1T (BF_WRELT+ 2*SZ_WRELT)
#define BF_FX2T (BF_FX1T + 2*SZ_F1)
#define BF_FY1T (BF_FX2T + 2*SZ_F2)
#define BF_FY2T (BF_FY1T + 2*SZ_F1)
#define BF_TOTAL (BF_FY2T+ 2*SZ_F2)
__device__ __align__(256) __nv_bfloat16 g_bf[BF_TOTAL];

// =================== helpers ===================
__device__ __forceinline__ uint32_t sptr(const void* p) {
    return (uint32_t)__cvta_generic_to_shared(p);
}
__device__ __forceinline__ void ldsm4(uint32_t r[4], const __nv_bfloat16* p) {
    uint32_t a = sptr(p);
    asm volatile("ldmatrix.sync.aligned.m8n8.x4.shared.b16 {%0,%1,%2,%3}, [%4];"
                 : "=r"(r[0]), "=r"(r[1]), "=r"(r[2]), "=r"(r[3]) : "r"(a));
}
__device__ __forceinline__ void mma16816(float c[4], const uint32_t a[4], uint32_t b0, uint32_t b1) {
    asm volatile(
        "mma.sync.aligned.m16n8k16.row.col.f32.bf16.bf16.f32 "
        "{%0,%1,%2,%3}, {%4,%5,%6,%7}, {%8,%9}, {%0,%1,%2,%3};"
        : "+f"(c[0]), "+f"(c[1]), "+f"(c[2]), "+f"(c[3])
        : "r"(a[0]), "r"(a[1]), "r"(a[2]), "r"(a[3]), "r"(b0), "r"(b1));
}
__device__ __forceinline__ void bsplit(float x, __nv_bfloat16& h, __nv_bfloat16& l) {
    h = __float2bfloat16(x);
    l = __float2bfloat16(x - __bfloat162float(h));
}
__device__ __forceinline__ void cpa16(uint32_t saddr, const void* g, bool pred) {
    int sz = pred ? 16 : 0;
    asm volatile("cp.async.cg.shared.global [%0], [%1], 16, %2;"
                 :: "r"(saddr), "l"(g), "r"(sz) : "memory");
}
__device__ __forceinline__ void cpa_commit() {
    asm volatile("cp.async.commit_group;" ::: "memory");
}
template<int NW> __device__ __forceinline__ void cpa_wait() {
    asm volatile("cp.async.wait_group %0;" :: "n"(NW) : "memory");
}
__device__ __forceinline__ float warpSum(float v) {
    #pragma unroll
    for (int o = 16; o; o >>= 1) v += __shfl_xor_sync(0xffffffffu, v, o);
    return v;
}
__device__ __forceinline__ float warpMax(float v) {
    #pragma unroll
    for (int o = 16; o; o >>= 1) v = fmaxf(v, __shfl_xor_sync(0xffffffffu, v, o));
    return v;
}

// =================== pre-split bf16 GEMM with cp.async ===================
#define SA   40
#define BTSZ (128 * SA)
#define BSTG (4 * BTSZ)
#define BSMEM (2 * BSTG * 2)

template <int BN, bool UAL>
__global__ __launch_bounds__(256, 2) void gemm_bf(
    const __nv_bfloat16* __restrict__ Ah, const __nv_bfloat16* __restrict__ Al,
    const __nv_bfloat16* __restrict__ Bh, const __nv_bfloat16* __restrict__ Bl,
    const float* __restrict__ bias, const float* __restrict__ Res,
    float* __restrict__ C, __nv_bfloat16* __restrict__ Chi, __nv_bfloat16* __restrict__ Clo,
    int M, int N, int K, int lda, int ldb, int ldc,
    long sAb, long sAh_, long sBb, long sBh_, long sCb, long sCh_, int Hn,
    float alpha, int doRelu)
{
    constexpr int NG = BN / 32;
    int z = blockIdx.z;
    int bb = z / Hn, hh = z % Hn;
    long ao = bb * sAb + hh * sAh_;
    long bo = bb * sBb + hh * sBh_;
    long co = bb * sCb + hh * sCh_;
    Ah += ao; if (UAL) Al += ao;
    Bh += bo; Bl += bo;
    if (C) C += co;
    if (Res) Res += co;
    if (Chi) Chi += co;
    if (Clo) Clo += co;

    extern __shared__ __nv_bfloat16 sm[];
    uint32_t sbase = sptr(sm);

    int m0 = blockIdx.y * 128;
    int n0 = blockIdx.x * BN;
    int tid = threadIdx.x, w = tid >> 5, lane = tid & 31;
    int wm = (w & 3) * 32;
    int wn = (w >> 2) * (BN / 2);

    float acc[2][2 * NG][4];
    #pragma unroll
    for (int f = 0; f < 2; f++)
        #pragma unroll
        for (int g = 0; g < 2 * NG; g++)
            #pragma unroll
            for (int e = 0; e < 4; e++) acc[f][g][e] = 0.f;

    int nk = K >> 5;

    auto issue = [&](int s, int buf) {
        int k0 = s << 5;
        uint32_t st = sbase + (uint32_t)buf * (BSTG * 2);
        constexpr int AIT = UAL ? 4 : 2;
        #pragma unroll
        for (int i = 0; i < AIT; i++) {
            int idx = tid + i * 256;
            int pl = idx >> 9, rem = idx & 511, row = rem >> 2, seg = rem & 3;
            const __nv_bfloat16* g = (pl ? Al : Ah) + (long)(m0 + row) * lda + k0 + seg * 8;
            cpa16(st + (uint32_t)(pl * BTSZ + row * SA + seg * 8) * 2, g, true);
        }
        constexpr int BIT = (BN * 8) / 256;
        #pragma unroll
        for (int i = 0; i < BIT; i++) {
            int idx = tid + i * 256;
            int pl = idx / (BN * 4), rem = idx % (BN * 4), row = rem >> 2, seg = rem & 3;
            int rg = n0 + row;
            int rc = (rg < N) ? rg : 0;
            const __nv_bfloat16* g = (pl ? Bl : Bh) + (long)rc * ldb + k0 + seg * 8;
            cpa16(st + (uint32_t)((2 + pl) * BTSZ + row * SA + seg * 8) * 2, g, rg < N);
        }
        cpa_commit();
    };

    issue(0, 0);
    issue(1, 1);

    for (int s = 0; s < nk; s++) {
        if (s + 2 <= nk) cpa_wait<1>(); else cpa_wait<0>();
        __syncthreads();

        const __nv_bfloat16* base = sm + (s & 1) * BSTG;
        const __nv_bfloat16* pAh = base;
        const __nv_bfloat16* pAl = base + BTSZ;
        const __nv_bfloat16* pBh = base + 2 * BTSZ;
        const __nv_bfloat16* pBl = base + 3 * BTSZ;

        #pragma unroll
        for (int kk = 0; kk < 32; kk += 16) {
            uint32_t ah[2][4], al[2][4];
            #pragma unroll
            for (int f = 0; f < 2; f++) {
                int r = wm + f * 16 + (lane & 15);
                int c = kk + ((lane >> 4) << 3);
                ldsm4(ah[f], pAh + r * SA + c);
                if (UAL) ldsm4(al[f], pAl + r * SA + c);
            }
            #pragma unroll
            for (int gp = 0; gp < NG; gp++) {
                int r = wn + gp * 16 + (lane & 7) + ((lane >> 4) << 3);
                int c = kk + (((lane >> 3) & 1) << 3);
                uint32_t th[4], tl[4];
                ldsm4(th, pBh + r * SA + c);
                ldsm4(tl, pBl + r * SA + c);
                #pragma unroll
                for (int f = 0; f < 2; f++) {
                    mma16816(acc[f][2*gp],   ah[f], th[0], th[1]);
                    if (UAL) mma16816(acc[f][2*gp], al[f], th[0], th[1]);
                    mma16816(acc[f][2*gp],   ah[f], tl[0], tl[1]);
                    mma16816(acc[f][2*gp+1], ah[f], th[2], th[3]);
                    if (UAL) mma16816(acc[f][2*gp+1], al[f], th[2], th[3]);
                    mma16816(acc[f][2*gp+1], ah[f], tl[2], tl[3]);
                }
            }
        }
        __syncthreads();
        if (s + 2 < nk) issue(s + 2, s & 1);
    }

    int gid = lane >> 2, tg = lane & 3;
    #pragma unroll
    for (int f = 0; f < 2; f++) {
        #pragma unroll
        for (int g = 0; g < 2 * NG; g++) {
            int r0 = m0 + wm + f * 16 + gid;
            int c0 = n0 + wn + g * 8 + tg * 2;
            #pragma unroll
            for (int e = 0; e < 4; e++) {
                int r = r0 + ((e >> 1) << 3);
                int c = c0 + (e & 1);
                if (c >= N) continue;
                float v = acc[f][g][e] * alpha;
                if (bias) v += bias[c];
                if (Res)  v += Res[(long)r * ldc + c];
                if (doRelu) v = fmaxf(v, 0.f);
                if (C) C[(long)r * ldc + c] = v;
                if (Chi) {
                    if (Clo) {
                        __nv_bfloat16 h, l;
                        bsplit(v, h, l);
                        Chi[(long)r * ldc + c] = h;
                        Clo[(long)r * ldc + c] = l;
                    } else {
                        Chi[(long)r * ldc + c] = __float2bfloat16(v);
                    }
                }
            }
        }
    }
}

// ---------------- LayerNorm ----------------
__global__ __launch_bounds__(256) void ln_k(const float* __restrict__ X,
                                            const float* __restrict__ g,
                                            const float* __restrict__ bta,
                                            float* __restrict__ Y,
                                            __nv_bfloat16* __restrict__ Yh,
                                            __nv_bfloat16* __restrict__ Yl)
{
    long row = blockIdx.x;
    const float* xr = X + row * PD;
    int t = threadIdx.x, lane = t & 31, wid = t >> 5;

    float s1 = 0.f, s2 = 0.f;
    for (int c = t; c < PD; c += 256) { float v = xr[c]; s1 += v; s2 += v * v; }
    s1 = warpSum(s1); s2 = warpSum(s2);
    __shared__ float sA[8], sB[8];
    if (lane == 0) { sA[wid] = s1; sB[wid] = s2; }
    __syncthreads();
    float t1 = 0.f, t2 = 0.f;
    #pragma unroll
    for (int wI = 0; wI < 8; wI++) { t1 += sA[wI]; t2 += sB[wI]; }
    float mean = t1 / (float)PD;
    float var  = t2 / (float)PD - mean * mean;
    float rs = rsqrtf(var + 1e-5f);
    for (int c = t; c < PD; c += 256) {
        float v = (xr[c] - mean) * rs * g[c] + bta[c];
        if (Y) Y[row * PD + c] = v;
        __nv_bfloat16 h, l;
        bsplit(v, h, l);
        Yh[row * PD + c] = h;
        Yl[row * PD + c] = l;
    }
}

// ---------------- elementwise split ----------------
__global__ void split_k(const float* __restrict__ in,
                        __nv_bfloat16* __restrict__ oh,
                        __nv_bfloat16* __restrict__ ol, long n)
{
    for (long i = blockIdx.x * (long)blockDim.x + threadIdx.x; i < n;
         i += (long)gridDim.x * blockDim.x) {
        __nv_bfloat16 h, l;
        bsplit(in[i], h, l);
        oh[i] = h; ol[i] = l;
    }
}

// ---------------- tiled transpose + split (fp32 -> bf16 planes) ----------------
__global__ void tsplit_k(const float* __restrict__ in,
                         __nv_bfloat16* __restrict__ oh,
                         __nv_bfloat16* __restrict__ ol,
                         int K, int N, int ldin,
                         long sinB, long sinH, long sout, int Hn)
{
    __shared__ float t[32][33];
    int z = blockIdx.z;
    int b = z / Hn, h = z % Hn;
    in += b * sinB + h * sinH;
    oh += (long)z * sout;
    if (ol) ol += (long)z * sout;
    int kb = blockIdx.y * 32, nb = blockIdx.x * 32;
    int tx = threadIdx.x, ty = threadIdx.y;
    #pragma unroll
    for (int j = 0; j < 32; j += 8) {
        int k = kb + ty + j, n = nb + tx;
        t[ty + j][tx] = (k < K && n < N) ? in[(long)k * ldin + n] : 0.f;
    }
    __syncthreads();
    #pragma unroll
    for (int j = 0; j < 32; j += 8) {
        int n = nb + ty + j, k = kb + tx;
        if (n < N && k < K) {
            __nv_bfloat16 hh, ll;
            bsplit(t[tx][ty + j], hh, ll);
            oh[(long)n * K + k] = hh;
            if (ol) ol[(long)n * K + k] = ll;
        }
    }
}

// ---------------- batched weight transpose+split with per-seg scale ----------------
struct WSegs {
    const float* src[12];
    __nv_bfloat16* oh[12];
    __nv_bfloat16* ol[12];
    int K[12];
    int N[12];
    float scale[12];
};
__global__ void wsplit_all(WSegs W)
{
    int seg = blockIdx.z;
    int K = W.K[seg], N = W.N[seg];
    int kb = blockIdx.y * 32, nb = blockIdx.x * 32;
    if (kb >= K || nb >= N) return;
    const float* in = W.src[seg];
    __nv_bfloat16* oh = W.oh[seg];
    __nv_bfloat16* ol = W.ol[seg];
    float sc = W.scale[seg];
    __shared__ float t[32][33];
    int tx = threadIdx.x, ty = threadIdx.y;
    #pragma unroll
    for (int j = 0; j < 32; j += 8) {
        int k = kb + ty + j, n = nb + tx;
        t[ty + j][tx] = (k < K && n < N) ? in[(long)k * N + n] * sc : 0.f;
    }
    __syncthreads();
    #pragma unroll
    for (int j = 0; j < 32; j += 8) {
        int n = nb + ty + j, k = kb + tx;
        if (n < N && k < K) {
            __nv_bfloat16 hh, ll;
            bsplit(t[tx][ty + j], hh, ll);
            oh[(long)n * K + k] = hh;
            ol[(long)n * K + k] = ll;
        }
    }
}

// ---------------- batched single-plane bf16 transpose ----------------
__global__ void bt_k(const __nv_bfloat16* __restrict__ ih,
                     __nv_bfloat16* __restrict__ oh,
                     int R, int Ccols)
{
    __shared__ unsigned short tb[32][33];
    long z = blockIdx.z;
    long off = z * (long)R * Ccols;
    ih += off; oh += off;
    int rb = blockIdx.y * 32, cb = blockIdx.x * 32;
    int tx = threadIdx.x, ty = threadIdx.y;
    #pragma unroll
    for (int j = 0; j < 32; j += 8) {
        int r = rb + ty + j, c = cb + tx;
        tb[ty + j][tx] = __bfloat16_as_ushort(ih[(long)r * Ccols + c]);
    }
    __syncthreads();
    #pragma unroll
    for (int j = 0; j < 32; j += 8) {
        int c = cb + ty + j, r = rb + tx;
        oh[(long)c * R + r] = __ushort_as_bfloat16(tb[tx][ty + j]);
    }
}

// ---------------- Enformer positional features -> bf16 planes ----------------
__global__ void pos_k(__nv_bfloat16* __restrict__ ph, __nv_bfloat16* __restrict__ pl)
{
    int m = blockIdx.x * blockDim.x + threadIdx.x;
    if (m >= PMQ) return;
    float d = (float)(m - (PN1 - 1));
    float ad = fabsf(d);

    float fe[16], fc[16], fg[16];
    float pmax = 0.f;
    const float ln2 = 0.6931471805599453f;
    #pragma unroll
    for (int i = 0; i < 16; i++) {
        float e = 3.0f + 8.0f * (float)i / 15.0f;
        float hl = exp2f(e);
        fe[i] = expf(-ln2 / hl * ad);
        float cw = exp2f((float)(i + 1)) - 1.0f;
        fc[i] = (cw > ad) ? 1.0f : 0.0f;
        float mean = 128.0f * (float)(i + 1);
        float conc = (mean / 64.0f) * (mean / 64.0f);
        float rate = mean / 4096.0f;
        float logp = (conc - 1.0f) * logf(ad) - rate * ad
                   - (lgammaf(conc) - conc * logf(rate));
        float prob = expf(logp) + 1e-8f;
        fg[i] = prob;
        pmax = fmaxf(pmax, prob);
    }
    float sgn = (d > 0.f) ? 1.f : ((d < 0.f) ? -1.f : 0.f);
    float inv = 1.0f / pmax;
    long base = (long)m * PNRP;
    #pragma unroll
    for (int i = 0; i < 16; i++) {
        float gv = fg[i] * inv;
        float vals[6] = { fe[i], fc[i], gv, sgn * fe[i], sgn * fc[i], sgn * gv };
        int offs[6] = { i, 16 + i, 32 + i, 48 + i, 64 + i, 80 + i };
        #pragma unroll
        for (int q = 0; q < 6; q++) {
            __nv_bfloat16 h, l;
            bsplit(vals[q], h, l);
            ph[base + offs[q]] = h;
            pl[base + offs[q]] = l;
        }
    }
}

// ---------------- kb = k*SCALE + rpb -> hi+lo planes (k region of merged KV) ----------------
__global__ void kb_k(const float* __restrict__ kv, const float* __restrict__ rpb,
                     __nv_bfloat16* __restrict__ kbh, __nv_bfloat16* __restrict__ kbl,
                     int total)
{
    for (int i = blockIdx.x * blockDim.x + threadIdx.x; i < total;
         i += gridDim.x * blockDim.x) {
        int r = i >> 9, c = i & 511;
        float v = kv[(long)r * NQV + c] * PSCALE + rpb[c];
        __nv_bfloat16 h, l;
        bsplit(v, h, l);
        kbh[i] = h; kbl[i] = l;
    }
}

// ---------------- tiled softmax ----------------
#define SMXSM (512 * 33 * 4)
__global__ __launch_bounds__(256) void softmax2_k(
    const float* __restrict__ att, const float* __restrict__ rel,
    __nv_bfloat16* __restrict__ ah)
{
    extern __shared__ float srel[];
    int i0 = blockIdx.x * 32;
    long z = blockIdx.y;
    const float* relz = rel + z * (long)PN2 * PMQ;
    int t = threadIdx.x;

    for (int idx = t; idx < PN2 * 32; idx += 256) {
        int j = idx >> 5, di = idx & 31;
        srel[j * 33 + di] = relz[(long)j * PMQ + (i0 + (PN2 - 1) - j) + di];
    }
    __syncthreads();

    int w = t >> 5, lane = t & 31;
    #pragma unroll
    for (int rr = 0; rr < 4; rr++) {
        int di = w + rr * 8;
        int i = i0 + di;
        long rowoff = (z * PN1 + i) * (long)PN2;
        const float* arow = att + rowoff;
        float v[16];
        float mx = -1e30f;
        #pragma unroll
        for (int u = 0; u < 16; u++) {
            int j = lane + u * 32;
            float val = arow[j] + srel[j * 33 + di];
            v[u] = val;
            mx = fmaxf(mx, val);
        }
        mx = warpMax(mx);
        float s = 0.f;
        #pragma unroll
        for (int u = 0; u < 16; u++) { v[u] = expf(v[u] - mx); s += v[u]; }
        s = warpSum(s);
        float inv = 1.0f / s;
        #pragma unroll
        for (int u = 0; u < 16; u++) {
            int j = lane + u * 32;
            ah[rowoff + j] = __float2bfloat16(v[u] * inv);
        }
    }
}

// ---------------- host orchestration ----------------
static inline dim3 ngrid(int M, int N, int BN, int Z) {
    return dim3((unsigned)((N + BN - 1) / BN), (unsigned)(M / 128), (unsigned)Z);
}

extern "C" void kernel_launch(void* const* d_in, const int* in_sizes, int n_in,
                              void* d_out, int out_size)
{
    const float* x     = (const float*)d_in[0];
    const float* y0    = (const float*)d_in[1];
    const float* W_res = (const float*)d_in[2];
    const float* lnx_g = (const float*)d_in[3];
    const float* lnx_b = (const float*)d_in[4];
    const float* lny_g = (const float*)d_in[5];
    const float* lny_b = (const float*)d_in[6];
    const float* Wq    = (const float*)d_in[7];
    const float* Wk    = (const float*)d_in[8];
    const float* Wv1   = (const float*)d_in[9];
    const float* Wv2   = (const float*)d_in[10];
    const float* Wo1   = (const float*)d_in[11];
    const float* bo1   = (const float*)d_in[12];
    const float* Wo2   = (const float*)d_in[13];
    const float* bo2   = (const float*)d_in[14];
    const float* Wrel  = (const float*)d_in[15];
    const float* rpb   = (const float*)d_in[16];
    const float* fx_g  = (const float*)d_in[17];
    const float* fx_b  = (const float*)d_in[18];
    const float* fx_w1 = (const float*)d_in[19];
    const float* fx_b1 = (const float*)d_in[20];
    const float* fx_w2 = (const float*)d_in[21];
    const float* fx_b2 = (const float*)d_in[22];
    const float* fy_g  = (const float*)d_in[23];
    const float* fy_b  = (const float*)d_in[24];
    const float* fy_w1 = (const float*)d_in[25];
    const float* fy_b1 = (const float*)d_in[26];
    const float* fy_w2 = (const float*)d_in[27];
    const float* fy_b2 = (const float*)d_in[28];

    cudaFuncSetAttribute(gemm_bf<128, true>,  cudaFuncAttributeMaxDynamicSharedMemorySize, BSMEM);
    cudaFuncSetAttribute(gemm_bf<128, false>, cudaFuncAttributeMaxDynamicSharedMemorySize, BSMEM);
    cudaFuncSetAttribute(gemm_bf<96, false>,  cudaFuncAttributeMaxDynamicSharedMemorySize, BSMEM);
    cudaFuncSetAttribute(softmax2_k, cudaFuncAttributeMaxDynamicSharedMemorySize, SMXSM);

    float* S = nullptr;
    cudaGetSymbolAddress((void**)&S, g_scratch);
    __nv_bfloat16* BF = nullptr;
    cudaGetSymbolAddress((void**)&BF, g_bf);

    float* gy   = S + OFF_Y;
    float* gqv  = S + OFF_QV;
    float* gkv  = S + OFF_KV;
    float* grel = S + OFF_REL;
    float* gatt = S + OFF_ATT;
    float* gx4  = S + OFF_X4;
    float* gy4  = S + OFF_Y4;

    #define PLH(off) (BF + (off))
    #define PLL(off, sz) (BF + (off) + (sz))

    float* outx = (float*)d_out;
    float* outy = outx + (long)PB * PN1 * PD;

    dim3 tt(32, 8);

    // ---- ALL weight transpose+splits in ONE launch; q scaled by PSCALE;
    //      q|v1 and k|v2 written into merged [1280, 768] plane buffers ----
    {
        WSegs Wg;
        __nv_bfloat16* QV1H = BF + BF_WQV1;
        __nv_bfloat16* QV1L = QV1H + SZ_WQV1;
        __nv_bfloat16* KV2H = BF + BF_WKV2;
        __nv_bfloat16* KV2L = KV2H + SZ_WKV2;
        const float* srcs[12] = { W_res, Wq, Wv1, Wk, Wv2, Wo1, Wo2, Wrel,
                                  fx_w1, fx_w2, fy_w1, fy_w2 };
        __nv_bfloat16* ohs[12] = {
            BF + BF_WRT, QV1H, QV1H + (long)HDK*PD, KV2H, KV2H + (long)HDK*PD,
            BF + BF_WO1T, BF + BF_WO2T, BF + BF_WRELT,
            BF + BF_FX1T, BF + BF_FX2T, BF + BF_FY1T, BF + BF_FY2T };
        __nv_bfloat16* ols[12] = {
            BF + BF_WRT + SZ_WRT, QV1L, QV1L + (long)HDK*PD, KV2L, KV2L + (long)HDK*PD,
            BF + BF_WO1T + SZ_WO1T, BF + BF_WO2T + SZ_WO2T, BF + BF_WRELT + SZ_WRELT,
            BF + BF_FX1T + SZ_F1, BF + BF_FX2T + SZ_F2, BF + BF_FY1T + SZ_F1,
            BF + BF_FY2T + SZ_F2 };
        int Ks[12] = { PDY0, PD, PD, PD, PD, HDV, HDV, PNRP, PD, PDFF, PD, PDFF };
        int Ns[12] = { PD, HDK, HDV, HDK, HDV, PD, PD, HDK, PDFF, PD, PDFF, PD };
        for (int i = 0; i < 12; i++) {
            Wg.src[i] = srcs[i];
            Wg.oh[i] = ohs[i];
            Wg.ol[i] = ols[i];
            Wg.K[i] = Ks[i];
            Wg.N[i] = Ns[i];
            Wg.scale[i] = (i == 1) ? PSCALE : 1.0f;
        }
        wsplit_all<<<dim3(48, 48, 12), tt>>>(Wg);
    }

    // ---- inputs ----
    ln_k<<<PB * PN1, 256>>>(x, lnx_g, lnx_b, nullptr, PLH(BF_X1), PLL(BF_X1,SZ_X1));
    split_k<<<2048, 256>>>(y0, PLH(BF_Y0), PLL(BF_Y0,SZ_Y0), SZ_Y0);

    // y = y0 @ W_res (3-pass)
    gemm_bf<128,true><<<ngrid(PB*PN2, PD, 128, 1), 256, BSMEM>>>(
        PLH(BF_Y0), PLL(BF_Y0,SZ_Y0), PLH(BF_WRT), PLL(BF_WRT,SZ_WRT),
        nullptr, nullptr, gy, nullptr, nullptr,
        PB*PN2, PD, PDY0, PDY0, PDY0, PD, 0,0,0,0,0,0, 1, 1.f, 0);
    ln_k<<<PB * PN2, 256>>>(gy, lny_g, lny_b, nullptr, PLH(BF_Y1), PLL(BF_Y1,SZ_Y1));

    // merged [q_scaled | v1] = x1 @ WQV1^T  (3-pass; fp32 + planes out, ldc=1280)
    gemm_bf<128,true><<<ngrid(PB*PN1, NQV, 128, 1), 256, BSMEM>>>(
        PLH(BF_X1), PLL(BF_X1,SZ_X1), PLH(BF_WQV1), PLL(BF_WQV1,SZ_WQV1),
        nullptr, nullptr, gqv, PLH(BF_QP), PLL(BF_QP,SZ_QV1),
        PB*PN1, NQV, PD, PD, PD, NQV, 0,0,0,0,0,0, 1, 1.f, 0);

    // merged [k | v2] = y1 @ WKV2^T  (3-pass)
    gemm_bf<128,true><<<ngrid(PB*PN2, NQV, 128, 1), 256, BSMEM>>>(
        PLH(BF_Y1), PLL(BF_Y1,SZ_Y1), PLH(BF_WKV2), PLL(BF_WKV2,SZ_WKV2),
        nullptr, nullptr, gkv, PLH(BF_KP), PLL(BF_KP,SZ_KV2),
        PB*PN2, NQV, PD, PD, PD, NQV, 0,0,0,0,0,0, 1, 1.f, 0);

    // v2T / v1T planes per (b,h) from merged fp32 buffers
    tsplit_k<<<dim3(PDV/32, PN2/32, PB*PH), tt>>>(
        gkv + HDK, PLH(BF_V2T), PLL(BF_V2T,SZ_V2T), PN2, PDV, NQV,
        (long)PN2*NQV, (long)PDV, (long)PDV*PN2, PH);
    tsplit_k<<<dim3(PDV/32, PN1/32, PB*PH), tt>>>(
        gqv + HDK, PLH(BF_V1T), PLL(BF_V1T,SZ_V1T), PN1, PDV, NQV,
        (long)PN1*NQV, (long)PDV, (long)PDV*PN1, PH);

    // pos features + rel_q (planes only; 3-pass)
    pos_k<<<(PMQ + 127) / 128, 128>>>(PLH(BF_POS), PLL(BF_POS,SZ_POS));
    gemm_bf<128,true><<<ngrid(PMQ, HDK, 128, 1), 256, BSMEM>>>(
        PLH(BF_POS), PLL(BF_POS,SZ_POS), PLH(BF_WRELT), PLL(BF_WRELT,SZ_WRELT),
        nullptr, nullptr, nullptr, PLH(BF_RQ), PLL(BF_RQ,SZ_RQ),
        PMQ, HDK, PNRP, PNRP, PNRP, HDK, 0,0,0,0,0,0, 1, 1.f, 0);

    // kb planes (hi+lo restored) from k region of gkv
    kb_k<<<2048, 256>>>(gkv, rpb, PLH(BF_KB), PLL(BF_KB,SZ_KB), PB*PN2*HDK);

    // content = q_scaled @ k^T  (3-pass; q/k planes strided at 1280)
    gemm_bf<128,true><<<ngrid(PN1, PN2, 128, PB*PH), 256, BSMEM>>>(
        PLH(BF_QP), PLL(BF_QP,SZ_QV1), PLH(BF_KP), PLL(BF_KP,SZ_KV2),
        nullptr, nullptr, gatt, nullptr, nullptr,
        PN1, PN2, PDK, NQV, NQV, PN2,
        (long)PN1*NQV, (long)PDK, (long)PN2*NQV, (long)PDK,
        (long)PH*PN1*PN2, (long)PN1*PN2, PH, 1.f, 0);

    // rel = kb @ rel_q^T  (3-pass restored)
    gemm_bf<128,true><<<ngrid(PN2, PMQ, 128, PB*PH), 256, BSMEM>>>(
        PLH(BF_KB), PLL(BF_KB,SZ_KB), PLH(BF_RQ), PLL(BF_RQ,SZ_RQ),
        nullptr, nullptr, grel, nullptr, nullptr,
        PN2, PMQ, PDK, HDK, HDK, PMQ,
        (long)PN2*HDK, (long)PDK, 0L, (long)PDK,
        (long)PH*PN2*PMQ, (long)PN2*PMQ, PH, 1.f, 0);

    // tiled softmax -> single bf16 plane
    softmax2_k<<<dim3(PN1/32, PB*PH), 256, SMXSM>>>(gatt, grel, PLH(BF_ATT));

    // attT (single plane)
    bt_k<<<dim3(PN2/32, PN1/32, PB*PH), tt>>>(PLH(BF_ATT), PLH(BF_ATTT), PN1, PN2);

    // out1 = attn @ v2  (2-pass on A; hi+lo output restored)
    gemm_bf<96,false><<<ngrid(PN1, PDV, 96, PB*PH), 256, BSMEM>>>(
        PLH(BF_ATT), nullptr, PLH(BF_V2T), PLL(BF_V2T,SZ_V2T),
        nullptr, nullptr, nullptr, PLH(BF_GO1), PLL(BF_GO1,SZ_GO1),
        PN1, PDV, PN2, PN2, PN2, HDV,
        (long)PH*PN1*PN2, (long)PN1*PN2, (long)PH*PDV*PN2, (long)PDV*PN2,
        (long)PN1*HDV, (long)PDV, PH, 1.f, 0);

    // out2 = attn^T @ v1 (2-pass on A; hi+lo output restored)
    gemm_bf<96,false><<<ngrid(PN2, PDV, 96, PB*PH), 256, BSMEM>>>(
        PLH(BF_ATTT), nullptr, PLH(BF_V1T), PLL(BF_V1T,SZ_V1T),
        nullptr, nullptr, nullptr, PLH(BF_GO2), PLL(BF_GO2,SZ_GO2),
        PN2, PDV, PN1, PN1, PN1, HDV,
        (long)PH*PN2*PN1, (long)PN2*PN1, (long)PH*PDV*PN1, (long)PDV*PN1,
        (long)PN2*HDV, (long)PDV, PH, 1.f, 0);

    // x4 = x + out1 @ Wo1 + bo1 ; y4 = y + out2 @ Wo2 + bo2  (3-pass restored)
    gemm_bf<128,true><<<ngrid(PB*PN1, PD, 128, 1), 256, BSMEM>>>(
        PLH(BF_GO1), PLL(BF_GO1,SZ_GO1), PLH(BF_WO1T), PLL(BF_WO1T,SZ_WO1T),
        bo1, x, gx4, nullptr, nullptr,
        PB*PN1, PD, HDV, HDV, HDV, PD, 0,0,0,0,0,0, 1, 1.f, 0);
    gemm_bf<128,true><<<ngrid(PB*PN2, PD, 128, 1), 256, BSMEM>>>(
        PLH(BF_GO2), PLL(BF_GO2,SZ_GO2), PLH(BF_WO2T), PLL(BF_WO2T,SZ_WO2T),
        bo2, gy, gy4, nullptr, nullptr,
        PB*PN2, PD, HDV, HDV, HDV, PD, 0,0,0,0,0,0, 1, 1.f, 0);

    // FFN x: hidden hi-only, FFN2 2-pass (kept)
    ln_k<<<PB * PN1, 256>>>(gx4, fx_g, fx_b, nullptr, PLH(BF_X1), PLL(BF_X1,SZ_X1));
    gemm_bf<128,true><<<ngrid(PB*PN1, PDFF, 128, 1), 256, BSMEM>>>(
        PLH(BF_X1), PLL(BF_X1,SZ_X1), PLH(BF_FX1T), PLL(BF_FX1T,SZ_F1),
        fx_b1, nullptr, nullptr, PLH(BF_GH), nullptr,
        PB*PN1, PDFF, PD, PD, PD, PDFF, 0,0,0,0,0,0, 1, 1.f, 1);
    gemm_bf<128,false><<<ngrid(PB*PN1, PD, 128, 1), 256, BSMEM>>>(
        PLH(BF_GH), nullptr, PLH(BF_FX2T), PLL(BF_FX2T,SZ_F2),
        fx_b2, gx4, outx, nullptr, nullptr,
        PB*PN1, PD, PDFF, PDFF, PDFF, PD, 0,0,0,0,0,0, 1, 1.f, 0);

    // FFN y
    ln_k<<<PB * PN2, 256>>>(gy4, fy_g, fy_b, nullptr, PLH(BF_Y1), PLL(BF_Y1,SZ_Y1));
    gemm_bf<128,true><<<ngrid(PB*PN2, PDFF, 128, 1), 256, BSMEM>>>(
        PLH(BF_Y1), PLL(BF_Y1,SZ_Y1), PLH(BF_FY1T), PLL(BF_FY1T,SZ_F1),
        fy_b1, nullptr, nullptr, PLH(BF_GH), nullptr,
        PB*PN2, PDFF, PD, PD, PD, PDFF, 0,0,0,0,0,0, 1, 1.f, 1);
    gemm_bf<128,false><<<ngrid(PB*PN2, PD, 128, 1), 256, BSMEM>>>(
        PLH(BF_GH), nullptr, PLH(BF_FY2T), PLL(BF_FY2T,SZ_F2),
        fy_b2, gy4, outy, nullptr, nullptr,
        PB*PN2, PD, PDFF, PDFF, PDFF, PD, 0,0,0,0,0,0, 1, 1.f, 0);

    (void)in_sizes; (void)n_in; (void)out_size;
}

// round 16
// speedup vs baseline: 1.1029x; 1.1029x over previous
#include <cuda_runtime.h>
#include <cuda_bf16.h>
#include <cstdint>
#include <math.h>

// ---------------- problem constants ----------------
#define PB   4
#define PN1  2048
#define PN2  512
#define PD   768
#define PH   8
#define PDK  64
#define PDV  96
#define PNRP 96
#define PDY0 1536
#define PDFF 1536
#define PMQ  2560
#define PSCALE 0.125f
#define HDK  512
#define HDV  768

// ---------------- fp32 scratch ----------------
#define OFF_Y      0L
#define OFF_Y1     (OFF_Y    + (long)PB*PN2*PD)
#define OFF_K      (OFF_Y1   + (long)PB*PN2*PD)
#define OFF_V1     (OFF_K    + (long)PB*PN2*HDK)
#define OFF_V2     (OFF_V1   + (long)PB*PN1*HDV)
#define OFF_REL    (OFF_V2   + (long)PB*PN2*HDV)
#define OFF_ATT    (OFF_REL  + (long)PB*PH*PN2*PMQ)
#define OFF_X4     (OFF_ATT  + (long)PB*PH*PN1*PN2)
#define OFF_Y4     (OFF_X4   + (long)PB*PN1*PD)
#define OFF_X1     (OFF_Y4   + (long)PB*PN2*PD)
#define SCRATCH_TOTAL (OFF_X1 + (long)PB*PN1*PD)
__device__ float g_scratch[SCRATCH_TOTAL];

// ---------------- bf16 plane scratch ----------------
#define SZ_X1   ((long)PB*PN1*PD)
#define SZ_Y1   ((long)PB*PN2*PD)
#define SZ_Y0   ((long)PB*PN2*PDY0)
#define SZ_Q    ((long)PB*PN1*HDK)
#define SZ_K    ((long)PB*PN2*HDK)
#define SZ_KB   ((long)PB*PN2*HDK)
#define SZ_RQ   ((long)PMQ*HDK)
#define SZ_ATT  ((long)PB*PH*PN1*PN2)
#define SZ_ATTT ((long)PB*PH*PN1*PN2)
#define SZ_V2T  ((long)PB*PH*PDV*PN2)
#define SZ_V1T  ((long)PB*PH*PDV*PN1)
#define SZ_GO1  ((long)PB*PN1*HDV)
#define SZ_GO2  ((long)PB*PN2*HDV)
#define SZ_GH   ((long)PB*PN1*PDFF)
#define SZ_POS  ((long)PMQ*PNRP)
#define SZ_WRT  ((long)PDY0*PD)
#define SZ_WRELT ((long)HDK*PNRP)
#define SZ_WQT  ((long)PD*HDK)
#define SZ_WKT  ((long)PD*HDK)
#define SZ_WV2T ((long)PD*HDV)
#define SZ_WV1T ((long)PD*HDV)
#define SZ_WO1T ((long)HDV*PD)
#define SZ_WO2T ((long)HDV*PD)
#define SZ_F1   ((long)PD*PDFF)
#define SZ_F2   ((long)PDFF*PD)

#define BF_X1   0L
#define BF_Y1   (BF_X1   + 2*SZ_X1)
#define BF_Y0   (BF_Y1   + 2*SZ_Y1)
#define BF_Q    (BF_Y0   + 2*SZ_Y0)
#define BF_K    (BF_Q    + 2*SZ_Q)
#define BF_KB   (BF_K    + 2*SZ_K)             // single plane
#define BF_RQ   (BF_KB   + SZ_KB)
#define BF_ATT  (BF_RQ   + 2*SZ_RQ)            // single plane
#define BF_ATTT (BF_ATT  + SZ_ATT)             // single plane
#define BF_V2T  (BF_ATTT + SZ_ATTT)
#define BF_V1T  (BF_V2T  + 2*SZ_V2T)
#define BF_GO1  (BF_V1T  + 2*SZ_V1T)           // single plane
#define BF_GO2  (BF_GO1  + SZ_GO1)             // single plane
#define BF_GH   (BF_GO2  + SZ_GO2)             // single plane
#define BF_POS  (BF_GH   + SZ_GH)
#define BF_WRT  (BF_POS  + 2*SZ_POS)
#define BF_WRELT (BF_WRT + 2*SZ_WRT)
#define BF_WQT  (BF_WRELT+ 2*SZ_WRELT)
#define BF_WKT  (BF_WQT  + 2*SZ_WQT)
#define BF_WV2T (BF_WKT  + 2*SZ_WKT)
#define BF_WV1T (BF_WV2T + 2*SZ_WV2T)
#define BF_WO1T (BF_WV1T + 2*SZ_WV1T)
#define BF_WO2T (BF_WO1T + 2*SZ_WO1T)
#define BF_FX1T (BF_WO2T + 2*SZ_WO2T)
#define BF_FX2T (BF_FX1T + 2*SZ_F1)
#define BF_FY1T (BF_FX2T + 2*SZ_F2)
#define BF_FY2T (BF_FY1T + 2*SZ_F1)
#define BF_TOTAL (BF_FY2T+ 2*SZ_F2)
__device__ __align__(256) __nv_bfloat16 g_bf[BF_TOTAL];

// =================== helpers ===================
__device__ __forceinline__ uint32_t sptr(const void* p) {
    return (uint32_t)__cvta_generic_to_shared(p);
}
__device__ __forceinline__ void ldsm4(uint32_t r[4], const __nv_bfloat16* p) {
    uint32_t a = sptr(p);
    asm volatile("ldmatrix.sync.aligned.m8n8.x4.shared.b16 {%0,%1,%2,%3}, [%4];"
                 : "=r"(r[0]), "=r"(r[1]), "=r"(r[2]), "=r"(r[3]) : "r"(a));
}
__device__ __forceinline__ void mma16816(float c[4], const uint32_t a[4], uint32_t b0, uint32_t b1) {
    asm volatile(
        "mma.sync.aligned.m16n8k16.row.col.f32.bf16.bf16.f32 "
        "{%0,%1,%2,%3}, {%4,%5,%6,%7}, {%8,%9}, {%0,%1,%2,%3};"
        : "+f"(c[0]), "+f"(c[1]), "+f"(c[2]), "+f"(c[3])
        : "r"(a[0]), "r"(a[1]), "r"(a[2]), "r"(a[3]), "r"(b0), "r"(b1));
}
__device__ __forceinline__ void bsplit(float x, __nv_bfloat16& h, __nv_bfloat16& l) {
    h = __float2bfloat16(x);
    l = __float2bfloat16(x - __bfloat162float(h));
}
__device__ __forceinline__ void cpa16(uint32_t saddr, const void* g, bool pred) {
    int sz = pred ? 16 : 0;
    asm volatile("cp.async.cg.shared.global [%0], [%1], 16, %2;"
                 :: "r"(saddr), "l"(g), "r"(sz) : "memory");
}
__device__ __forceinline__ void cpa_commit() {
    asm volatile("cp.async.commit_group;" ::: "memory");
}
template<int NW> __device__ __forceinline__ void cpa_wait() {
    asm volatile("cp.async.wait_group %0;" :: "n"(NW) : "memory");
}
__device__ __forceinline__ float warpSum(float v) {
    #pragma unroll
    for (int o = 16; o; o >>= 1) v += __shfl_xor_sync(0xffffffffu, v, o);
    return v;
}
__device__ __forceinline__ float warpMax(float v) {
    #pragma unroll
    for (int o = 16; o; o >>= 1) v = fmaxf(v, __shfl_xor_sync(0xffffffffu, v, o));
    return v;
}

// =================== pre-split bf16 GEMM with cp.async ===================
// C = alpha*(A @ B^T) (+bias)(+Res)(relu). A=[M,K] planes (lo optional via UAL),
// B=[N,K] planes, k-contig. C fp32 optional; Chi (and Clo) planes optional.
// CTA tile 128 x BN (BN in {128, 96, 64}), BK=32, 8 warps 4m x 2n.
// 2-stage cp.async ring. M%128==0, K%32==0; N guarded vs BN grid.
#define SA   40
#define BTSZ (128 * SA)
#define BSTG (4 * BTSZ)
#define BSMEM (2 * BSTG * 2)

template <int BN, bool UAL>
__global__ __launch_bounds__(256, 2) void gemm_bf(
    const __nv_bfloat16* __restrict__ Ah, const __nv_bfloat16* __restrict__ Al,
    const __nv_bfloat16* __restrict__ Bh, const __nv_bfloat16* __restrict__ Bl,
    const float* __restrict__ bias, const float* __restrict__ Res,
    float* __restrict__ C, __nv_bfloat16* __restrict__ Chi, __nv_bfloat16* __restrict__ Clo,
    int M, int N, int K, int lda, int ldb, int ldc,
    long sAb, long sAh_, long sBb, long sBh_, long sCb, long sCh_, int Hn,
    float alpha, int doRelu)
{
    constexpr int NG = BN / 32;
    int z = blockIdx.z;
    int bb = z / Hn, hh = z % Hn;
    long ao = bb * sAb + hh * sAh_;
    long bo = bb * sBb + hh * sBh_;
    long co = bb * sCb + hh * sCh_;
    Ah += ao; if (UAL) Al += ao;
    Bh += bo; Bl += bo;
    if (C) C += co;
    if (Res) Res += co;
    if (Chi) Chi += co;
    if (Clo) Clo += co;

    extern __shared__ __nv_bfloat16 sm[];
    uint32_t sbase = sptr(sm);

    int m0 = blockIdx.y * 128;
    int n0 = blockIdx.x * BN;
    int tid = threadIdx.x, w = tid >> 5, lane = tid & 31;
    int wm = (w & 3) * 32;
    int wn = (w >> 2) * (BN / 2);

    float acc[2][2 * NG][4];
    #pragma unroll
    for (int f = 0; f < 2; f++)
        #pragma unroll
        for (int g = 0; g < 2 * NG; g++)
            #pragma unroll
            for (int e = 0; e < 4; e++) acc[f][g][e] = 0.f;

    int nk = K >> 5;

    auto issue = [&](int s, int buf) {
        int k0 = s << 5;
        uint32_t st = sbase + (uint32_t)buf * (BSTG * 2);
        constexpr int AIT = UAL ? 4 : 2;
        #pragma unroll
        for (int i = 0; i < AIT; i++) {
            int idx = tid + i * 256;
            int pl = idx >> 9, rem = idx & 511, row = rem >> 2, seg = rem & 3;
            const __nv_bfloat16* g = (pl ? Al : Ah) + (long)(m0 + row) * lda + k0 + seg * 8;
            cpa16(st + (uint32_t)(pl * BTSZ + row * SA + seg * 8) * 2, g, true);
        }
        constexpr int BIT = (BN * 8) / 256;
        #pragma unroll
        for (int i = 0; i < BIT; i++) {
            int idx = tid + i * 256;
            int pl = idx / (BN * 4), rem = idx % (BN * 4), row = rem >> 2, seg = rem & 3;
            int rg = n0 + row;
            int rc = (rg < N) ? rg : 0;
            const __nv_bfloat16* g = (pl ? Bl : Bh) + (long)rc * ldb + k0 + seg * 8;
            cpa16(st + (uint32_t)((2 + pl) * BTSZ + row * SA + seg * 8) * 2, g, rg < N);
        }
        cpa_commit();
    };

    issue(0, 0);
    issue(1, 1);

    for (int s = 0; s < nk; s++) {
        if (s + 2 <= nk) cpa_wait<1>(); else cpa_wait<0>();
        __syncthreads();

        const __nv_bfloat16* base = sm + (s & 1) * BSTG;
        const __nv_bfloat16* pAh = base;
        const __nv_bfloat16* pAl = base + BTSZ;
        const __nv_bfloat16* pBh = base + 2 * BTSZ;
        const __nv_bfloat16* pBl = base + 3 * BTSZ;

        #pragma unroll
        for (int kk = 0; kk < 32; kk += 16) {
            uint32_t ah[2][4], al[2][4];
            #pragma unroll
            for (int f = 0; f < 2; f++) {
                int r = wm + f * 16 + (lane & 15);
                int c = kk + ((lane >> 4) << 3);
                ldsm4(ah[f], pAh + r * SA + c);
                if (UAL) ldsm4(al[f], pAl + r * SA + c);
            }
            #pragma unroll
            for (int gp = 0; gp < NG; gp++) {
                int r = wn + gp * 16 + (lane & 7) + ((lane >> 4) << 3);
                int c = kk + (((lane >> 3) & 1) << 3);
                uint32_t th[4], tl[4];
                ldsm4(th, pBh + r * SA + c);
                ldsm4(tl, pBl + r * SA + c);
                #pragma unroll
                for (int f = 0; f < 2; f++) {
                    mma16816(acc[f][2*gp],   ah[f], th[0], th[1]);
                    if (UAL) mma16816(acc[f][2*gp], al[f], th[0], th[1]);
                    mma16816(acc[f][2*gp],   ah[f], tl[0], tl[1]);
                    mma16816(acc[f][2*gp+1], ah[f], th[2], th[3]);
                    if (UAL) mma16816(acc[f][2*gp+1], al[f], th[2], th[3]);
                    mma16816(acc[f][2*gp+1], ah[f], tl[2], tl[3]);
                }
            }
        }
        __syncthreads();
        if (s + 2 < nk) issue(s + 2, s & 1);
    }

    int gid = lane >> 2, tg = lane & 3;
    #pragma unroll
    for (int f = 0; f < 2; f++) {
        #pragma unroll
        for (int g = 0; g < 2 * NG; g++) {
            int r0 = m0 + wm + f * 16 + gid;
            int c0 = n0 + wn + g * 8 + tg * 2;
            #pragma unroll
            for (int e = 0; e < 4; e++) {
                int r = r0 + ((e >> 1) << 3);
                int c = c0 + (e & 1);
                if (c >= N) continue;
                float v = acc[f][g][e] * alpha;
                if (bias) v += bias[c];
                if (Res)  v += Res[(long)r * ldc + c];
                if (doRelu) v = fmaxf(v, 0.f);
                if (C) C[(long)r * ldc + c] = v;
                if (Chi) {
                    if (Clo) {
                        __nv_bfloat16 h, l;
                        bsplit(v, h, l);
                        Chi[(long)r * ldc + c] = h;
                        Clo[(long)r * ldc + c] = l;
                    } else {
                        Chi[(long)r * ldc + c] = __float2bfloat16(v);
                    }
                }
            }
        }
    }
}

// ---------------- LayerNorm ----------------
__global__ __launch_bounds__(256) void ln_k(const float* __restrict__ X,
                                            const float* __restrict__ g,
                                            const float* __restrict__ bta,
                                            float* __restrict__ Y,
                                            __nv_bfloat16* __restrict__ Yh,
                                            __nv_bfloat16* __restrict__ Yl)
{
    long row = blockIdx.x;
    const float* xr = X + row * PD;
    int t = threadIdx.x, lane = t & 31, wid = t >> 5;

    float s1 = 0.f, s2 = 0.f;
    for (int c = t; c < PD; c += 256) { float v = xr[c]; s1 += v; s2 += v * v; }
    s1 = warpSum(s1); s2 = warpSum(s2);
    __shared__ float sA[8], sB[8];
    if (lane == 0) { sA[wid] = s1; sB[wid] = s2; }
    __syncthreads();
    float t1 = 0.f, t2 = 0.f;
    #pragma unroll
    for (int wI = 0; wI < 8; wI++) { t1 += sA[wI]; t2 += sB[wI]; }
    float mean = t1 / (float)PD;
    float var  = t2 / (float)PD - mean * mean;
    float rs = rsqrtf(var + 1e-5f);
    for (int c = t; c < PD; c += 256) {
        float v = (xr[c] - mean) * rs * g[c] + bta[c];
        if (Y) Y[row * PD + c] = v;
        __nv_bfloat16 h, l;
        bsplit(v, h, l);
        Yh[row * PD + c] = h;
        Yl[row * PD + c] = l;
    }
}

// ---------------- elementwise split ----------------
__global__ void split_k(const float* __restrict__ in,
                        __nv_bfloat16* __restrict__ oh,
                        __nv_bfloat16* __restrict__ ol, long n)
{
    for (long i = blockIdx.x * (long)blockDim.x + threadIdx.x; i < n;
         i += (long)gridDim.x * blockDim.x) {
        __nv_bfloat16 h, l;
        bsplit(in[i], h, l);
        oh[i] = h; ol[i] = l;
    }
}

// ---------------- tiled transpose + split (fp32 -> bf16 planes) ----------------
__global__ void tsplit_k(const float* __restrict__ in,
                         __nv_bfloat16* __restrict__ oh,
                         __nv_bfloat16* __restrict__ ol,
                         int K, int N, int ldin,
                         long sinB, long sinH, long sout, int Hn)
{
    __shared__ float t[32][33];
    int z = blockIdx.z;
    int b = z / Hn, h = z % Hn;
    in += b * sinB + h * sinH;
    oh += (long)z * sout;
    if (ol) ol += (long)z * sout;
    int kb = blockIdx.y * 32, nb = blockIdx.x * 32;
    int tx = threadIdx.x, ty = threadIdx.y;
    #pragma unroll
    for (int j = 0; j < 32; j += 8) {
        int k = kb + ty + j, n = nb + tx;
        t[ty + j][tx] = (k < K && n < N) ? in[(long)k * ldin + n] : 0.f;
    }
    __syncthreads();
    #pragma unroll
    for (int j = 0; j < 32; j += 8) {
        int n = nb + ty + j, k = kb + tx;
        if (n < N && k < K) {
            __nv_bfloat16 hh, ll;
            bsplit(t[tx][ty + j], hh, ll);
            oh[(long)n * K + k] = hh;
            if (ol) ol[(long)n * K + k] = ll;
        }
    }
}

// ---------------- batched weight transpose+split (all 12 weights, 1 launch) ----------------
struct WSegs {
    const float* src[12];
    __nv_bfloat16* oh[12];
    __nv_bfloat16* ol[12];
    int K[12];
    int N[12];
};
__global__ void wsplit_all(WSegs W)
{
    int seg = blockIdx.z;
    int K = W.K[seg], N = W.N[seg];
    int kb = blockIdx.y * 32, nb = blockIdx.x * 32;
    if (kb >= K || nb >= N) return;
    const float* in = W.src[seg];
    __nv_bfloat16* oh = W.oh[seg];
    __nv_bfloat16* ol = W.ol[seg];
    __shared__ float t[32][33];
    int tx = threadIdx.x, ty = threadIdx.y;
    #pragma unroll
    for (int j = 0; j < 32; j += 8) {
        int k = kb + ty + j, n = nb + tx;
        t[ty + j][tx] = (k < K && n < N) ? in[(long)k * N + n] : 0.f;
    }
    __syncthreads();
    #pragma unroll
    for (int j = 0; j < 32; j += 8) {
        int n = nb + ty + j, k = kb + tx;
        if (n < N && k < K) {
            __nv_bfloat16 hh, ll;
            bsplit(t[tx][ty + j], hh, ll);
            oh[(long)n * K + k] = hh;
            ol[(long)n * K + k] = ll;
        }
    }
}

// ---------------- batched single-plane bf16 transpose ----------------
__global__ void bt_k(const __nv_bfloat16* __restrict__ ih,
                     __nv_bfloat16* __restrict__ oh,
                     int R, int Ccols)
{
    __shared__ unsigned short tb[32][33];
    long z = blockIdx.z;
    long off = z * (long)R * Ccols;
    ih += off; oh += off;
    int rb = blockIdx.y * 32, cb = blockIdx.x * 32;
    int tx = threadIdx.x, ty = threadIdx.y;
    #pragma unroll
    for (int j = 0; j < 32; j += 8) {
        int r = rb + ty + j, c = cb + tx;
        tb[ty + j][tx] = __bfloat16_as_ushort(ih[(long)r * Ccols + c]);
    }
    __syncthreads();
    #pragma unroll
    for (int j = 0; j < 32; j += 8) {
        int c = cb + ty + j, r = rb + tx;
        oh[(long)c * R + r] = __ushort_as_bfloat16(tb[tx][ty + j]);
    }
}

// ---------------- Enformer positional features -> bf16 planes ----------------
__global__ void pos_k(__nv_bfloat16* __restrict__ ph, __nv_bfloat16* __restrict__ pl)
{
    int m = blockIdx.x * blockDim.x + threadIdx.x;
    if (m >= PMQ) return;
    float d = (float)(m - (PN1 - 1));
    float ad = fabsf(d);

    float fe[16], fc[16], fg[16];
    float pmax = 0.f;
    const float ln2 = 0.6931471805599453f;
    #pragma unroll
    for (int i = 0; i < 16; i++) {
        float e = 3.0f + 8.0f * (float)i / 15.0f;
        float hl = exp2f(e);
        fe[i] = expf(-ln2 / hl * ad);
        float cw = exp2f((float)(i + 1)) - 1.0f;
        fc[i] = (cw > ad) ? 1.0f : 0.0f;
        float mean = 128.0f * (float)(i + 1);
        float conc = (mean / 64.0f) * (mean / 64.0f);
        float rate = mean / 4096.0f;
        float logp = (conc - 1.0f) * logf(ad) - rate * ad
                   - (lgammaf(conc) - conc * logf(rate));
        float prob = expf(logp) + 1e-8f;
        fg[i] = prob;
        pmax = fmaxf(pmax, prob);
    }
    float sgn = (d > 0.f) ? 1.f : ((d < 0.f) ? -1.f : 0.f);
    float inv = 1.0f / pmax;
    long base = (long)m * PNRP;
    #pragma unroll
    for (int i = 0; i < 16; i++) {
        float gv = fg[i] * inv;
        float vals[6] = { fe[i], fc[i], gv, sgn * fe[i], sgn * fc[i], sgn * gv };
        int offs[6] = { i, 16 + i, 32 + i, 48 + i, 64 + i, 80 + i };
        #pragma unroll
        for (int q = 0; q < 6; q++) {
            __nv_bfloat16 h, l;
            bsplit(vals[q], h, l);
            ph[base + offs[q]] = h;
            pl[base + offs[q]] = l;
        }
    }
}

// ---------------- kb = k*SCALE + rpb -> single bf16 plane ----------------
__global__ void kb_k(const float* __restrict__ k, const float* __restrict__ rpb,
                     __nv_bfloat16* __restrict__ kbh, int total)
{
    for (int i = blockIdx.x * blockDim.x + threadIdx.x; i < total;
         i += gridDim.x * blockDim.x)
        kbh[i] = __float2bfloat16(k[i] * PSCALE + rpb[i & 511]);
}

// ---------------- tiled softmax ----------------
#define SMXSM (512 * 33 * 4)
__global__ __launch_bounds__(256) void softmax2_k(
    const float* __restrict__ att, const float* __restrict__ rel,
    __nv_bfloat16* __restrict__ ah)
{
    extern __shared__ float srel[];
    int i0 = blockIdx.x * 32;
    long z = blockIdx.y;
    const float* relz = rel + z * (long)PN2 * PMQ;
    int t = threadIdx.x;

    for (int idx = t; idx < PN2 * 32; idx += 256) {
        int j = idx >> 5, di = idx & 31;
        srel[j * 33 + di] = relz[(long)j * PMQ + (i0 + (PN2 - 1) - j) + di];
    }
    __syncthreads();

    int w = t >> 5, lane = t & 31;
    #pragma unroll
    for (int rr = 0; rr < 4; rr++) {
        int di = w + rr * 8;
        int i = i0 + di;
        long rowoff = (z * PN1 + i) * (long)PN2;
        const float* arow = att + rowoff;
        float v[16];
        float mx = -1e30f;
        #pragma unroll
        for (int u = 0; u < 16; u++) {
            int j = lane + u * 32;
            float val = arow[j] + srel[j * 33 + di];
            v[u] = val;
            mx = fmaxf(mx, val);
        }
        mx = warpMax(mx);
        float s = 0.f;
        #pragma unroll
        for (int u = 0; u < 16; u++) { v[u] = expf(v[u] - mx); s += v[u]; }
        s = warpSum(s);
        float inv = 1.0f / s;
        #pragma unroll
        for (int u = 0; u < 16; u++) {
            int j = lane + u * 32;
            ah[rowoff + j] = __float2bfloat16(v[u] * inv);
        }
    }
}

// ---------------- host orchestration ----------------
static inline dim3 ngrid(int M, int N, int BN, int Z) {
    return dim3((unsigned)((N + BN - 1) / BN), (unsigned)(M / 128), (unsigned)Z);
}

extern "C" void kernel_launch(void* const* d_in, const int* in_sizes, int n_in,
                              void* d_out, int out_size)
{
    const float* x     = (const float*)d_in[0];
    const float* y0    = (const float*)d_in[1];
    const float* W_res = (const float*)d_in[2];
    const float* lnx_g = (const float*)d_in[3];
    const float* lnx_b = (const float*)d_in[4];
    const float* lny_g = (const float*)d_in[5];
    const float* lny_b = (const float*)d_in[6];
    const float* Wq    = (const float*)d_in[7];
    const float* Wk    = (const float*)d_in[8];
    const float* Wv1   = (const float*)d_in[9];
    const float* Wv2   = (const float*)d_in[10];
    const float* Wo1   = (const float*)d_in[11];
    const float* bo1   = (const float*)d_in[12];
    const float* Wo2   = (const float*)d_in[13];
    const float* bo2   = (const float*)d_in[14];
    const float* Wrel  = (const float*)d_in[15];
    const float* rpb   = (const float*)d_in[16];
    const float* fx_g  = (const float*)d_in[17];
    const float* fx_b  = (const float*)d_in[18];
    const float* fx_w1 = (const float*)d_in[19];
    const float* fx_b1 = (const float*)d_in[20];
    const float* fx_w2 = (const float*)d_in[21];
    const float* fx_b2 = (const float*)d_in[22];
    const float* fy_g  = (const float*)d_in[23];
    const float* fy_b  = (const float*)d_in[24];
    const float* fy_w1 = (const float*)d_in[25];
    const float* fy_b1 = (const float*)d_in[26];
    const float* fy_w2 = (const float*)d_in[27];
    const float* fy_b2 = (const float*)d_in[28];

    cudaFuncSetAttribute(gemm_bf<128, true>,  cudaFuncAttributeMaxDynamicSharedMemorySize, BSMEM);
    cudaFuncSetAttribute(gemm_bf<128, false>, cudaFuncAttributeMaxDynamicSharedMemorySize, BSMEM);
    cudaFuncSetAttribute(gemm_bf<96, false>,  cudaFuncAttributeMaxDynamicSharedMemorySize, BSMEM);
    cudaFuncSetAttribute(gemm_bf<64, true>,   cudaFuncAttributeMaxDynamicSharedMemorySize, BSMEM);
    cudaFuncSetAttribute(gemm_bf<64, false>,  cudaFuncAttributeMaxDynamicSharedMemorySize, BSMEM);
    cudaFuncSetAttribute(softmax2_k, cudaFuncAttributeMaxDynamicSharedMemorySize, SMXSM);

    float* S = nullptr;
    cudaGetSymbolAddress((void**)&S, g_scratch);
    __nv_bfloat16* BF = nullptr;
    cudaGetSymbolAddress((void**)&BF, g_bf);

    float* gy   = S + OFF_Y;
    float* gx1  = S + OFF_X1;
    float* gy1  = S + OFF_Y1;
    float* gk   = S + OFF_K;
    float* gv1  = S + OFF_V1;
    float* gv2  = S + OFF_V2;
    float* grel = S + OFF_REL;
    float* gatt = S + OFF_ATT;
    float* gx4  = S + OFF_X4;
    float* gy4  = S + OFF_Y4;

    #define PLH(off) (BF + (off))
    #define PLL(off, sz) (BF + (off) + (sz))

    float* outx = (float*)d_out;
    float* outy = outx + (long)PB * PN1 * PD;

    dim3 tt(32, 8);

    // ---- ALL weight transpose+splits in ONE launch ----
    {
        WSegs Wg;
        const float* srcs[12] = { W_res, Wq, Wk, Wv2, Wv1, Wo1, Wo2, Wrel,
                                  fx_w1, fx_w2, fy_w1, fy_w2 };
        long ohs[12] = { BF_WRT, BF_WQT, BF_WKT, BF_WV2T, BF_WV1T, BF_WO1T, BF_WO2T, BF_WRELT,
                         BF_FX1T, BF_FX2T, BF_FY1T, BF_FY2T };
        long szs[12] = { SZ_WRT, SZ_WQT, SZ_WKT, SZ_WV2T, SZ_WV1T, SZ_WO1T, SZ_WO2T, SZ_WRELT,
                         SZ_F1, SZ_F2, SZ_F1, SZ_F2 };
        int Ks[12] = { PDY0, PD, PD, PD, PD, HDV, HDV, PNRP, PD, PDFF, PD, PDFF };
        int Ns[12] = { PD, HDK, HDK, HDV, HDV, PD, PD, HDK, PDFF, PD, PDFF, PD };
        for (int i = 0; i < 12; i++) {
            Wg.src[i] = srcs[i];
            Wg.oh[i] = BF + ohs[i];
            Wg.ol[i] = BF + ohs[i] + szs[i];
            Wg.K[i] = Ks[i];
            Wg.N[i] = Ns[i];
        }
        wsplit_all<<<dim3(48, 48, 12), tt>>>(Wg);
    }

    // ---- inputs ----
    ln_k<<<PB * PN1, 256>>>(x, lnx_g, lnx_b, gx1, PLH(BF_X1), PLL(BF_X1,SZ_X1));
    split_k<<<2048, 256>>>(y0, PLH(BF_Y0), PLL(BF_Y0,SZ_Y0), SZ_Y0);

    // y = y0 @ W_res  (3-pass; BN=64 for fill: 192 blocks)
    gemm_bf<64,true><<<ngrid(PB*PN2, PD, 64, 1), 256, BSMEM>>>(
        PLH(BF_Y0), PLL(BF_Y0,SZ_Y0), PLH(BF_WRT), PLL(BF_WRT,SZ_WRT),
        nullptr, nullptr, gy, nullptr, nullptr,
        PB*PN2, PD, PDY0, PDY0, PDY0, PD, 0,0,0,0,0,0, 1, 1.f, 0);
    ln_k<<<PB * PN2, 256>>>(gy, lny_g, lny_b, gy1, PLH(BF_Y1), PLL(BF_Y1,SZ_Y1));

    // q (pre-scaled, planes only; 3-pass), k (3-pass, BN=64), v2 (2-pass, BN=64), v1 (2-pass)
    gemm_bf<128,true><<<ngrid(PB*PN1, HDK, 128, 1), 256, BSMEM>>>(
        PLH(BF_X1), PLL(BF_X1,SZ_X1), PLH(BF_WQT), PLL(BF_WQT,SZ_WQT),
        nullptr, nullptr, nullptr, PLH(BF_Q), PLL(BF_Q,SZ_Q),
        PB*PN1, HDK, PD, PD, PD, HDK, 0,0,0,0,0,0, 1, PSCALE, 0);
    gemm_bf<64,true><<<ngrid(PB*PN2, HDK, 64, 1), 256, BSMEM>>>(
        PLH(BF_Y1), PLL(BF_Y1,SZ_Y1), PLH(BF_WKT), PLL(BF_WKT,SZ_WKT),
        nullptr, nullptr, gk, PLH(BF_K), PLL(BF_K,SZ_K),
        PB*PN2, HDK, PD, PD, PD, HDK, 0,0,0,0,0,0, 1, 1.f, 0);
    gemm_bf<64,false><<<ngrid(PB*PN2, HDV, 64, 1), 256, BSMEM>>>(
        PLH(BF_Y1), nullptr, PLH(BF_WV2T), PLL(BF_WV2T,SZ_WV2T),
        nullptr, nullptr, gv2, nullptr, nullptr,
        PB*PN2, HDV, PD, PD, PD, HDV, 0,0,0,0,0,0, 1, 1.f, 0);
    gemm_bf<128,false><<<ngrid(PB*PN1, HDV, 128, 1), 256, BSMEM>>>(
        PLH(BF_X1), nullptr, PLH(BF_WV1T), PLL(BF_WV1T,SZ_WV1T),
        nullptr, nullptr, gv1, nullptr, nullptr,
        PB*PN1, HDV, PD, PD, PD, HDV, 0,0,0,0,0,0, 1, 1.f, 0);

    // v2T / v1T planes per (b,h)
    tsplit_k<<<dim3(PDV/32, PN2/32, PB*PH), tt>>>(
        gv2, PLH(BF_V2T), PLL(BF_V2T,SZ_V2T), PN2, PDV, HDV,
        (long)PN2*HDV, (long)PDV, (long)PDV*PN2, PH);
    tsplit_k<<<dim3(PDV/32, PN1/32, PB*PH), tt>>>(
        gv1, PLH(BF_V1T), PLL(BF_V1T,SZ_V1T), PN1, PDV, HDV,
        (long)PN1*HDV, (long)PDV, (long)PDV*PN1, PH);

    // pos features + rel_q (planes only; 3-pass; BN=64: 160 blocks)
    pos_k<<<(PMQ + 127) / 128, 128>>>(PLH(BF_POS), PLL(BF_POS,SZ_POS));
    gemm_bf<64,true><<<ngrid(PMQ, HDK, 64, 1), 256, BSMEM>>>(
        PLH(BF_POS), PLL(BF_POS,SZ_POS), PLH(BF_WRELT), PLL(BF_WRELT,SZ_WRELT),
        nullptr, nullptr, nullptr, PLH(BF_RQ), PLL(BF_RQ,SZ_RQ),
        PMQ, HDK, PNRP, PNRP, PNRP, HDK, 0,0,0,0,0,0, 1, 1.f, 0);

    // kb single plane
    kb_k<<<2048, 256>>>(gk, rpb, PLH(BF_KB), PB*PN2*HDK);

    // content = q_scaled @ k^T  (3-pass)
    gemm_bf<128,true><<<ngrid(PN1, PN2, 128, PB*PH), 256, BSMEM>>>(
        PLH(BF_Q), PLL(BF_Q,SZ_Q), PLH(BF_K), PLL(BF_K,SZ_K),
        nullptr, nullptr, gatt, nullptr, nullptr,
        PN1, PN2, PDK, HDK, HDK, PN2,
        (long)PN1*HDK, (long)PDK, (long)PN2*HDK, (long)PDK,
        (long)PH*PN1*PN2, (long)PN1*PN2, PH, 1.f, 0);

    // rel = kb @ rel_q^T  (2-pass: kb single plane)
    gemm_bf<128,false><<<ngrid(PN2, PMQ, 128, PB*PH), 256, BSMEM>>>(
        PLH(BF_KB), nullptr, PLH(BF_RQ), PLL(BF_RQ,SZ_RQ),
        nullptr, nullptr, grel, nullptr, nullptr,
        PN2, PMQ, PDK, HDK, HDK, PMQ,
        (long)PN2*HDK, (long)PDK, 0L, (long)PDK,
        (long)PH*PN2*PMQ, (long)PN2*PMQ, PH, 1.f, 0);

    // tiled softmax -> single bf16 plane
    softmax2_k<<<dim3(PN1/32, PB*PH), 256, SMXSM>>>(gatt, grel, PLH(BF_ATT));

    // attT (single plane)
    bt_k<<<dim3(PN2/32, PN1/32, PB*PH), tt>>>(PLH(BF_ATT), PLH(BF_ATTT), PN1, PN2);

    // out1 = attn @ v2  (2-pass; hi-only output)
    gemm_bf<96,false><<<ngrid(PN1, PDV, 96, PB*PH), 256, BSMEM>>>(
        PLH(BF_ATT), nullptr, PLH(BF_V2T), PLL(BF_V2T,SZ_V2T),
        nullptr, nullptr, nullptr, PLH(BF_GO1), nullptr,
        PN1, PDV, PN2, PN2, PN2, HDV,
        (long)PH*PN1*PN2, (long)PN1*PN2, (long)PH*PDV*PN2, (long)PDV*PN2,
        (long)PN1*HDV, (long)PDV, PH, 1.f, 0);

    // out2 = attn^T @ v1 (2-pass; hi-only output)
    gemm_bf<96,false><<<ngrid(PN2, PDV, 96, PB*PH), 256, BSMEM>>>(
        PLH(BF_ATTT), nullptr, PLH(BF_V1T), PLL(BF_V1T,SZ_V1T),
        nullptr, nullptr, nullptr, PLH(BF_GO2), nullptr,
        PN2, PDV, PN1, PN1, PN1, HDV,
        (long)PH*PN2*PN1, (long)PN2*PN1, (long)PH*PDV*PN1, (long)PDV*PN1,
        (long)PN2*HDV, (long)PDV, PH, 1.f, 0);

    // x4 = x + out1 @ Wo1 + bo1 ; y4 = y + out2 @ Wo2 + bo2  (2-pass; Wo2 BN=64)
    gemm_bf<128,false><<<ngrid(PB*PN1, PD, 128, 1), 256, BSMEM>>>(
        PLH(BF_GO1), nullptr, PLH(BF_WO1T), PLL(BF_WO1T,SZ_WO1T),
        bo1, x, gx4, nullptr, nullptr,
        PB*PN1, PD, HDV, HDV, HDV, PD, 0,0,0,0,0,0, 1, 1.f, 0);
    gemm_bf<64,false><<<ngrid(PB*PN2, PD, 64, 1), 256, BSMEM>>>(
        PLH(BF_GO2), nullptr, PLH(BF_WO2T), PLL(BF_WO2T,SZ_WO2T),
        bo2, gy, gy4, nullptr, nullptr,
        PB*PN2, PD, HDV, HDV, HDV, PD, 0,0,0,0,0,0, 1, 1.f, 0);

    // FFN x: hidden hi-only, FFN2 2-pass
    ln_k<<<PB * PN1, 256>>>(gx4, fx_g, fx_b, gx1, PLH(BF_X1), PLL(BF_X1,SZ_X1));
    gemm_bf<128,true><<<ngrid(PB*PN1, PDFF, 128, 1), 256, BSMEM>>>(
        PLH(BF_X1), PLL(BF_X1,SZ_X1), PLH(BF_FX1T), PLL(BF_FX1T,SZ_F1),
        fx_b1, nullptr, nullptr, PLH(BF_GH), nullptr,
        PB*PN1, PDFF, PD, PD, PD, PDFF, 0,0,0,0,0,0, 1, 1.f, 1);
    gemm_bf<128,false><<<ngrid(PB*PN1, PD, 128, 1), 256, BSMEM>>>(
        PLH(BF_GH), nullptr, PLH(BF_FX2T), PLL(BF_FX2T,SZ_F2),
        fx_b2, gx4, outx, nullptr, nullptr,
        PB*PN1, PD, PDFF, PDFF, PDFF, PD, 0,0,0,0,0,0, 1, 1.f, 0);

    // FFN y: FFN2 BN=64 for fill
    ln_k<<<PB * PN2, 256>>>(gy4, fy_g, fy_b, gy1, PLH(BF_Y1), PLL(BF_Y1,SZ_Y1));
    gemm_bf<128,true><<<ngrid(PB*PN2, PDFF, 128, 1), 256, BSMEM>>>(
        PLH(BF_Y1), PLL(BF_Y1,SZ_Y1), PLH(BF_FY1T), PLL(BF_FY1T,SZ_F1),
        fy_b1, nullptr, nullptr, PLH(BF_GH), nullptr,
        PB*PN2, PDFF, PD, PD, PD, PDFF, 0,0,0,0,0,0, 1, 1.f, 1);
    gemm_bf<64,false><<<ngrid(PB*PN2, PD, 64, 1), 256, BSMEM>>>(
        PLH(BF_GH), nullptr, PLH(BF_FY2T), PLL(BF_FY2T,SZ_F2),
        fy_b2, gy4, outy, nullptr, nullptr,
        PB*PN2, PD, PDFF, PDFF, PDFF, PD, 0,0,0,0,0,0, 1, 1.f, 0);

    (void)in_sizes; (void)n_in; (void)out_size;
}

// round 17
// speedup vs baseline: 1.1047x; 1.0016x over previous
#include <cuda_runtime.h>
#include <cuda_bf16.h>
#include <cstdint>
#include <math.h>

// ---------------- problem constants ----------------
#define PB   4
#define PN1  2048
#define PN2  512
#define PD   768
#define PH   8
#define PDK  64
#define PDV  96
#define PNRP 96
#define PDY0 1536
#define PDFF 1536
#define PMQ  2560
#define PSCALE 0.125f
#define HDK  512
#define HDV  768

// ---------------- fp32 scratch ----------------
#define OFF_Y      0L
#define OFF_Y1     (OFF_Y    + (long)PB*PN2*PD)
#define OFF_K      (OFF_Y1   + (long)PB*PN2*PD)
#define OFF_V1     (OFF_K    + (long)PB*PN2*HDK)
#define OFF_V2     (OFF_V1   + (long)PB*PN1*HDV)
#define OFF_REL    (OFF_V2   + (long)PB*PN2*HDV)
#define OFF_ATT    (OFF_REL  + (long)PB*PH*PN2*PMQ)
#define OFF_X4     (OFF_ATT  + (long)PB*PH*PN1*PN2)
#define OFF_Y4     (OFF_X4   + (long)PB*PN1*PD)
#define OFF_X1     (OFF_Y4   + (long)PB*PN2*PD)
#define SCRATCH_TOTAL (OFF_X1 + (long)PB*PN1*PD)
__device__ float g_scratch[SCRATCH_TOTAL];

// ---------------- bf16 plane scratch ----------------
#define SZ_X1   ((long)PB*PN1*PD)
#define SZ_Y1   ((long)PB*PN2*PD)
#define SZ_Y0   ((long)PB*PN2*PDY0)
#define SZ_Q    ((long)PB*PN1*HDK)
#define SZ_K    ((long)PB*PN2*HDK)
#define SZ_KB   ((long)PB*PN2*HDK)
#define SZ_RQ   ((long)PMQ*HDK)
#define SZ_ATT  ((long)PB*PH*PN1*PN2)
#define SZ_ATTT ((long)PB*PH*PN1*PN2)
#define SZ_V2T  ((long)PB*PH*PDV*PN2)
#define SZ_V1T  ((long)PB*PH*PDV*PN1)
#define SZ_GO1  ((long)PB*PN1*HDV)
#define SZ_GO2  ((long)PB*PN2*HDV)
#define SZ_GH   ((long)PB*PN1*PDFF)
#define SZ_POS  ((long)PMQ*PNRP)
#define SZ_WRT  ((long)PDY0*PD)
#define SZ_WRELT ((long)HDK*PNRP)
#define SZ_WQT  ((long)PD*HDK)
#define SZ_WKT  ((long)PD*HDK)
#define SZ_WV2T ((long)PD*HDV)
#define SZ_WV1T ((long)PD*HDV)
#define SZ_WO1T ((long)HDV*PD)
#define SZ_WO2T ((long)HDV*PD)
#define SZ_F1   ((long)PD*PDFF)
#define SZ_F2   ((long)PDFF*PD)

#define BF_X1   0L
#define BF_Y1   (BF_X1   + 2*SZ_X1)
#define BF_Y0   (BF_Y1   + 2*SZ_Y1)
#define BF_Q    (BF_Y0   + 2*SZ_Y0)
#define BF_K    (BF_Q    + 2*SZ_Q)
#define BF_KB   (BF_K    + 2*SZ_K)             // single plane
#define BF_RQ   (BF_KB   + SZ_KB)
#define BF_ATT  (BF_RQ   + 2*SZ_RQ)            // single plane
#define BF_ATTT (BF_ATT  + SZ_ATT)             // single plane
#define BF_V2T  (BF_ATTT + SZ_ATTT)
#define BF_V1T  (BF_V2T  + 2*SZ_V2T)
#define BF_GO1  (BF_V1T  + 2*SZ_V1T)           // single plane
#define BF_GO2  (BF_GO1  + SZ_GO1)             // single plane
#define BF_GH   (BF_GO2  + SZ_GO2)             // single plane
#define BF_POS  (BF_GH   + SZ_GH)
#define BF_WRT  (BF_POS  + 2*SZ_POS)
#define BF_WRELT (BF_WRT + 2*SZ_WRT)
#define BF_WQT  (BF_WRELT+ 2*SZ_WRELT)
#define BF_WKT  (BF_WQT  + 2*SZ_WQT)
#define BF_WV2T (BF_WKT  + 2*SZ_WKT)
#define BF_WV1T (BF_WV2T + 2*SZ_WV2T)
#define BF_WO1T (BF_WV1T + 2*SZ_WV1T)
#define BF_WO2T (BF_WO1T + 2*SZ_WO1T)
#define BF_FX1T (BF_WO2T + 2*SZ_WO2T)
#define BF_FX2T (BF_FX1T + 2*SZ_F1)
#define BF_FY1T (BF_FX2T + 2*SZ_F2)
#define BF_FY2T (BF_FY1T + 2*SZ_F1)
#define BF_TOTAL (BF_FY2T+ 2*SZ_F2)
__device__ __align__(256) __nv_bfloat16 g_bf[BF_TOTAL];

// =================== helpers ===================
__device__ __forceinline__ uint32_t sptr(const void* p) {
    return (uint32_t)__cvta_generic_to_shared(p);
}
__device__ __forceinline__ void ldsm4(uint32_t r[4], const __nv_bfloat16* p) {
    uint32_t a = sptr(p);
    asm volatile("ldmatrix.sync.aligned.m8n8.x4.shared.b16 {%0,%1,%2,%3}, [%4];"
                 : "=r"(r[0]), "=r"(r[1]), "=r"(r[2]), "=r"(r[3]) : "r"(a));
}
__device__ __forceinline__ void mma16816(float c[4], const uint32_t a[4], uint32_t b0, uint32_t b1) {
    asm volatile(
        "mma.sync.aligned.m16n8k16.row.col.f32.bf16.bf16.f32 "
        "{%0,%1,%2,%3}, {%4,%5,%6,%7}, {%8,%9}, {%0,%1,%2,%3};"
        : "+f"(c[0]), "+f"(c[1]), "+f"(c[2]), "+f"(c[3])
        : "r"(a[0]), "r"(a[1]), "r"(a[2]), "r"(a[3]), "r"(b0), "r"(b1));
}
__device__ __forceinline__ void bsplit(float x, __nv_bfloat16& h, __nv_bfloat16& l) {
    h = __float2bfloat16(x);
    l = __float2bfloat16(x - __bfloat162float(h));
}
__device__ __forceinline__ void cpa16(uint32_t saddr, const void* g, bool pred) {
    int sz = pred ? 16 : 0;
    asm volatile("cp.async.cg.shared.global [%0], [%1], 16, %2;"
                 :: "r"(saddr), "l"(g), "r"(sz) : "memory");
}
__device__ __forceinline__ void cpa_commit() {
    asm volatile("cp.async.commit_group;" ::: "memory");
}
template<int NW> __device__ __forceinline__ void cpa_wait() {
    asm volatile("cp.async.wait_group %0;" :: "n"(NW) : "memory");
}
__device__ __forceinline__ float warpSum(float v) {
    #pragma unroll
    for (int o = 16; o; o >>= 1) v += __shfl_xor_sync(0xffffffffu, v, o);
    return v;
}
__device__ __forceinline__ float warpMax(float v) {
    #pragma unroll
    for (int o = 16; o; o >>= 1) v = fmaxf(v, __shfl_xor_sync(0xffffffffu, v, o));
    return v;
}

// =================== pre-split bf16 GEMM with cp.async ===================
// C = alpha*(A @ B^T) (+bias)(+Res)(relu). A=[M,K] planes (lo optional via UAL),
// B=[N,K] planes, k-contig. C fp32 optional; Chi (and Clo) planes optional.
// CTA tile 128 x BN (BN in {128, 96, 64}), BK=32, 8 warps 4m x 2n.
// 2-stage cp.async ring; smem stage sized to (2*128 + 2*BN)*SA halfwords so
// BN<=96 fits 3 CTAs/SM. M%128==0, K%32==0; N guarded vs BN grid.
#define SA   40
#define BTSZ (128 * SA)

template <int BN> struct GemmCfg {
    static constexpr int STG  = (2 * 128 + 2 * BN) * SA;  // halfwords per stage
    static constexpr int SMEM = 2 * STG * 2;              // bytes
    static constexpr int MAXC = (BN == 128) ? 2 : 3;
};

template <int BN, bool UAL>
__global__ __launch_bounds__(256, GemmCfg<BN>::MAXC) void gemm_bf(
    const __nv_bfloat16* __restrict__ Ah, const __nv_bfloat16* __restrict__ Al,
    const __nv_bfloat16* __restrict__ Bh, const __nv_bfloat16* __restrict__ Bl,
    const float* __restrict__ bias, const float* __restrict__ Res,
    float* __restrict__ C, __nv_bfloat16* __restrict__ Chi, __nv_bfloat16* __restrict__ Clo,
    int M, int N, int K, int lda, int ldb, int ldc,
    long sAb, long sAh_, long sBb, long sBh_, long sCb, long sCh_, int Hn,
    float alpha, int doRelu)
{
    constexpr int NG = BN / 32;
    constexpr int STG = GemmCfg<BN>::STG;
    int z = blockIdx.z;
    int bb = z / Hn, hh = z % Hn;
    long ao = bb * sAb + hh * sAh_;
    long bo = bb * sBb + hh * sBh_;
    long co = bb * sCb + hh * sCh_;
    Ah += ao; if (UAL) Al += ao;
    Bh += bo; Bl += bo;
    if (C) C += co;
    if (Res) Res += co;
    if (Chi) Chi += co;
    if (Clo) Clo += co;

    extern __shared__ __nv_bfloat16 sm[];
    uint32_t sbase = sptr(sm);

    int m0 = blockIdx.y * 128;
    int n0 = blockIdx.x * BN;
    int tid = threadIdx.x, w = tid >> 5, lane = tid & 31;
    int wm = (w & 3) * 32;
    int wn = (w >> 2) * (BN / 2);

    float acc[2][2 * NG][4];
    #pragma unroll
    for (int f = 0; f < 2; f++)
        #pragma unroll
        for (int g = 0; g < 2 * NG; g++)
            #pragma unroll
            for (int e = 0; e < 4; e++) acc[f][g][e] = 0.f;

    int nk = K >> 5;

    auto issue = [&](int s, int buf) {
        int k0 = s << 5;
        uint32_t st = sbase + (uint32_t)buf * (STG * 2);
        constexpr int AIT = UAL ? 4 : 2;
        #pragma unroll
        for (int i = 0; i < AIT; i++) {
            int idx = tid + i * 256;
            int pl = idx >> 9, rem = idx & 511, row = rem >> 2, seg = rem & 3;
            const __nv_bfloat16* g = (pl ? Al : Ah) + (long)(m0 + row) * lda + k0 + seg * 8;
            cpa16(st + (uint32_t)(pl * BTSZ + row * SA + seg * 8) * 2, g, true);
        }
        constexpr int BIT = (BN * 8) / 256;
        #pragma unroll
        for (int i = 0; i < BIT; i++) {
            int idx = tid + i * 256;
            int pl = idx / (BN * 4), rem = idx % (BN * 4), row = rem >> 2, seg = rem & 3;
            int rg = n0 + row;
            int rc = (rg < N) ? rg : 0;
            const __nv_bfloat16* g = (pl ? Bl : Bh) + (long)rc * ldb + k0 + seg * 8;
            cpa16(st + (uint32_t)(2 * BTSZ + pl * (BN * SA) + row * SA + seg * 8) * 2,
                  g, rg < N);
        }
        cpa_commit();
    };

    issue(0, 0);
    issue(1, 1);

    for (int s = 0; s < nk; s++) {
        if (s + 2 <= nk) cpa_wait<1>(); else cpa_wait<0>();
        __syncthreads();

        const __nv_bfloat16* base = sm + (s & 1) * STG;
        const __nv_bfloat16* pAh = base;
        const __nv_bfloat16* pAl = base + BTSZ;
        const __nv_bfloat16* pBh = base + 2 * BTSZ;
        const __nv_bfloat16* pBl = base + 2 * BTSZ + BN * SA;

        #pragma unroll
        for (int kk = 0; kk < 32; kk += 16) {
            uint32_t ah[2][4], al[2][4];
            #pragma unroll
            for (int f = 0; f < 2; f++) {
                int r = wm + f * 16 + (lane & 15);
                int c = kk + ((lane >> 4) << 3);
                ldsm4(ah[f], pAh + r * SA + c);
                if (UAL) ldsm4(al[f], pAl + r * SA + c);
            }
            #pragma unroll
            for (int gp = 0; gp < NG; gp++) {
                int r = wn + gp * 16 + (lane & 7) + ((lane >> 4) << 3);
                int c = kk + (((lane >> 3) & 1) << 3);
                uint32_t th[4], tl[4];
                ldsm4(th, pBh + r * SA + c);
                ldsm4(tl, pBl + r * SA + c);
                #pragma unroll
                for (int f = 0; f < 2; f++) {
                    mma16816(acc[f][2*gp],   ah[f], th[0], th[1]);
                    if (UAL) mma16816(acc[f][2*gp], al[f], th[0], th[1]);
                    mma16816(acc[f][2*gp],   ah[f], tl[0], tl[1]);
                    mma16816(acc[f][2*gp+1], ah[f], th[2], th[3]);
                    if (UAL) mma16816(acc[f][2*gp+1], al[f], th[2], th[3]);
                    mma16816(acc[f][2*gp+1], ah[f], tl[2], tl[3]);
                }
            }
        }
        __syncthreads();
        if (s + 2 < nk) issue(s + 2, s & 1);
    }

    int gid = lane >> 2, tg = lane & 3;
    #pragma unroll
    for (int f = 0; f < 2; f++) {
        #pragma unroll
        for (int g = 0; g < 2 * NG; g++) {
            int r0 = m0 + wm + f * 16 + gid;
            int c0 = n0 + wn + g * 8 + tg * 2;
            #pragma unroll
            for (int e = 0; e < 4; e++) {
                int r = r0 + ((e >> 1) << 3);
                int c = c0 + (e & 1);
                if (c >= N) continue;
                float v = acc[f][g][e] * alpha;
                if (bias) v += bias[c];
                if (Res)  v += Res[(long)r * ldc + c];
                if (doRelu) v = fmaxf(v, 0.f);
                if (C) C[(long)r * ldc + c] = v;
                if (Chi) {
                    if (Clo) {
                        __nv_bfloat16 h, l;
                        bsplit(v, h, l);
                        Chi[(long)r * ldc + c] = h;
                        Clo[(long)r * ldc + c] = l;
                    } else {
                        Chi[(long)r * ldc + c] = __float2bfloat16(v);
                    }
                }
            }
        }
    }
}

// ---------------- LayerNorm ----------------
__global__ __launch_bounds__(256) void ln_k(const float* __restrict__ X,
                                            const float* __restrict__ g,
                                            const float* __restrict__ bta,
                                            float* __restrict__ Y,
                                            __nv_bfloat16* __restrict__ Yh,
                                            __nv_bfloat16* __restrict__ Yl)
{
    long row = blockIdx.x;
    const float* xr = X + row * PD;
    int t = threadIdx.x, lane = t & 31, wid = t >> 5;

    float s1 = 0.f, s2 = 0.f;
    for (int c = t; c < PD; c += 256) { float v = xr[c]; s1 += v; s2 += v * v; }
    s1 = warpSum(s1); s2 = warpSum(s2);
    __shared__ float sA[8], sB[8];
    if (lane == 0) { sA[wid] = s1; sB[wid] = s2; }
    __syncthreads();
    float t1 = 0.f, t2 = 0.f;
    #pragma unroll
    for (int wI = 0; wI < 8; wI++) { t1 += sA[wI]; t2 += sB[wI]; }
    float mean = t1 / (float)PD;
    float var  = t2 / (float)PD - mean * mean;
    float rs = rsqrtf(var + 1e-5f);
    for (int c = t; c < PD; c += 256) {
        float v = (xr[c] - mean) * rs * g[c] + bta[c];
        if (Y) Y[row * PD + c] = v;
        __nv_bfloat16 h, l;
        bsplit(v, h, l);
        Yh[row * PD + c] = h;
        Yl[row * PD + c] = l;
    }
}

// ---------------- elementwise split ----------------
__global__ void split_k(const float* __restrict__ in,
                        __nv_bfloat16* __restrict__ oh,
                        __nv_bfloat16* __restrict__ ol, long n)
{
    for (long i = blockIdx.x * (long)blockDim.x + threadIdx.x; i < n;
         i += (long)gridDim.x * blockDim.x) {
        __nv_bfloat16 h, l;
        bsplit(in[i], h, l);
        oh[i] = h; ol[i] = l;
    }
}

// ---------------- tiled transpose + split (fp32 -> bf16 planes) ----------------
__global__ void tsplit_k(const float* __restrict__ in,
                         __nv_bfloat16* __restrict__ oh,
                         __nv_bfloat16* __restrict__ ol,
                         int K, int N, int ldin,
                         long sinB, long sinH, long sout, int Hn)
{
    __shared__ float t[32][33];
    int z = blockIdx.z;
    int b = z / Hn, h = z % Hn;
    in += b * sinB + h * sinH;
    oh += (long)z * sout;
    if (ol) ol += (long)z * sout;
    int kb = blockIdx.y * 32, nb = blockIdx.x * 32;
    int tx = threadIdx.x, ty = threadIdx.y;
    #pragma unroll
    for (int j = 0; j < 32; j += 8) {
        int k = kb + ty + j, n = nb + tx;
        t[ty + j][tx] = (k < K && n < N) ? in[(long)k * ldin + n] : 0.f;
    }
    __syncthreads();
    #pragma unroll
    for (int j = 0; j < 32; j += 8) {
        int n = nb + ty + j, k = kb + tx;
        if (n < N && k < K) {
            __nv_bfloat16 hh, ll;
            bsplit(t[tx][ty + j], hh, ll);
            oh[(long)n * K + k] = hh;
            if (ol) ol[(long)n * K + k] = ll;
        }
    }
}

// ---------------- batched weight transpose+split (all 12 weights, 1 launch) ----------------
struct WSegs {
    const float* src[12];
    __nv_bfloat16* oh[12];
    __nv_bfloat16* ol[12];
    int K[12];
    int N[12];
};
__global__ void wsplit_all(WSegs W)
{
    int seg = blockIdx.z;
    int K = W.K[seg], N = W.N[seg];
    int kb = blockIdx.y * 32, nb = blockIdx.x * 32;
    if (kb >= K || nb >= N) return;
    const float* in = W.src[seg];
    __nv_bfloat16* oh = W.oh[seg];
    __nv_bfloat16* ol = W.ol[seg];
    __shared__ float t[32][33];
    int tx = threadIdx.x, ty = threadIdx.y;
    #pragma unroll
    for (int j = 0; j < 32; j += 8) {
        int k = kb + ty + j, n = nb + tx;
        t[ty + j][tx] = (k < K && n < N) ? in[(long)k * N + n] : 0.f;
    }
    __syncthreads();
    #pragma unroll
    for (int j = 0; j < 32; j += 8) {
        int n = nb + ty + j, k = kb + tx;
        if (n < N && k < K) {
            __nv_bfloat16 hh, ll;
            bsplit(t[tx][ty + j], hh, ll);
            oh[(long)n * K + k] = hh;
            ol[(long)n * K + k] = ll;
        }
    }
}

// ---------------- batched single-plane bf16 transpose ----------------
__global__ void bt_k(const __nv_bfloat16* __restrict__ ih,
                     __nv_bfloat16* __restrict__ oh,
                     int R, int Ccols)
{
    __shared__ unsigned short tb[32][33];
    long z = blockIdx.z;
    long off = z * (long)R * Ccols;
    ih += off; oh += off;
    int rb = blockIdx.y * 32, cb = blockIdx.x * 32;
    int tx = threadIdx.x, ty = threadIdx.y;
    #pragma unroll
    for (int j = 0; j < 32; j += 8) {
        int r = rb + ty + j, c = cb + tx;
        tb[ty + j][tx] = __bfloat16_as_ushort(ih[(long)r * Ccols + c]);
    }
    __syncthreads();
    #pragma unroll
    for (int j = 0; j < 32; j += 8) {
        int c = cb + ty + j, r = rb + tx;
        oh[(long)c * R + r] = __ushort_as_bfloat16(tb[tx][ty + j]);
    }
}

// ---------------- Enformer positional features -> bf16 planes ----------------
__global__ void pos_k(__nv_bfloat16* __restrict__ ph, __nv_bfloat16* __restrict__ pl)
{
    int m = blockIdx.x * blockDim.x + threadIdx.x;
    if (m >= PMQ) return;
    float d = (float)(m - (PN1 - 1));
    float ad = fabsf(d);

    float fe[16], fc[16], fg[16];
    float pmax = 0.f;
    const float ln2 = 0.6931471805599453f;
    #pragma unroll
    for (int i = 0; i < 16; i++) {
        float e = 3.0f + 8.0f * (float)i / 15.0f;
        float hl = exp2f(e);
        fe[i] = expf(-ln2 / hl * ad);
        float cw = exp2f((float)(i + 1)) - 1.0f;
        fc[i] = (cw > ad) ? 1.0f : 0.0f;
        float mean = 128.0f * (float)(i + 1);
        float conc = (mean / 64.0f) * (mean / 64.0f);
        float rate = mean / 4096.0f;
        float logp = (conc - 1.0f) * logf(ad) - rate * ad
                   - (lgammaf(conc) - conc * logf(rate));
        float prob = expf(logp) + 1e-8f;
        fg[i] = prob;
        pmax = fmaxf(pmax, prob);
    }
    float sgn = (d > 0.f) ? 1.f : ((d < 0.f) ? -1.f : 0.f);
    float inv = 1.0f / pmax;
    long base = (long)m * PNRP;
    #pragma unroll
    for (int i = 0; i < 16; i++) {
        float gv = fg[i] * inv;
        float vals[6] = { fe[i], fc[i], gv, sgn * fe[i], sgn * fc[i], sgn * gv };
        int offs[6] = { i, 16 + i, 32 + i, 48 + i, 64 + i, 80 + i };
        #pragma unroll
        for (int q = 0; q < 6; q++) {
            __nv_bfloat16 h, l;
            bsplit(vals[q], h, l);
            ph[base + offs[q]] = h;
            pl[base + offs[q]] = l;
        }
    }
}

// ---------------- kb = k*SCALE + rpb -> single bf16 plane ----------------
__global__ void kb_k(const float* __restrict__ k, const float* __restrict__ rpb,
                     __nv_bfloat16* __restrict__ kbh, int total)
{
    for (int i = blockIdx.x * blockDim.x + threadIdx.x; i < total;
         i += gridDim.x * blockDim.x)
        kbh[i] = __float2bfloat16(k[i] * PSCALE + rpb[i & 511]);
}

// ---------------- tiled softmax ----------------
#define SMXSM (512 * 33 * 4)
__global__ __launch_bounds__(256) void softmax2_k(
    const float* __restrict__ att, const float* __restrict__ rel,
    __nv_bfloat16* __restrict__ ah)
{
    extern __shared__ float srel[];
    int i0 = blockIdx.x * 32;
    long z = blockIdx.y;
    const float* relz = rel + z * (long)PN2 * PMQ;
    int t = threadIdx.x;

    for (int idx = t; idx < PN2 * 32; idx += 256) {
        int j = idx >> 5, di = idx & 31;
        srel[j * 33 + di] = relz[(long)j * PMQ + (i0 + (PN2 - 1) - j) + di];
    }
    __syncthreads();

    int w = t >> 5, lane = t & 31;
    #pragma unroll
    for (int rr = 0; rr < 4; rr++) {
        int di = w + rr * 8;
        int i = i0 + di;
        long rowoff = (z * PN1 + i) * (long)PN2;
        const float* arow = att + rowoff;
        float v[16];
        float mx = -1e30f;
        #pragma unroll
        for (int u = 0; u < 16; u++) {
            int j = lane + u * 32;
            float val = arow[j] + srel[j * 33 + di];
            v[u] = val;
            mx = fmaxf(mx, val);
        }
        mx = warpMax(mx);
        float s = 0.f;
        #pragma unroll
        for (int u = 0; u < 16; u++) { v[u] = expf(v[u] - mx); s += v[u]; }
        s = warpSum(s);
        float inv = 1.0f / s;
        #pragma unroll
        for (int u = 0; u < 16; u++) {
            int j = lane + u * 32;
            ah[rowoff + j] = __float2bfloat16(v[u] * inv);
        }
    }
}

// ---------------- host orchestration ----------------
static inline dim3 ngrid(int M, int N, int BN, int Z) {
    return dim3((unsigned)((N + BN - 1) / BN), (unsigned)(M / 128), (unsigned)Z);
}

extern "C" void kernel_launch(void* const* d_in, const int* in_sizes, int n_in,
                              void* d_out, int out_size)
{
    const float* x     = (const float*)d_in[0];
    const float* y0    = (const float*)d_in[1];
    const float* W_res = (const float*)d_in[2];
    const float* lnx_g = (const float*)d_in[3];
    const float* lnx_b = (const float*)d_in[4];
    const float* lny_g = (const float*)d_in[5];
    const float* lny_b = (const float*)d_in[6];
    const float* Wq    = (const float*)d_in[7];
    const float* Wk    = (const float*)d_in[8];
    const float* Wv1   = (const float*)d_in[9];
    const float* Wv2   = (const float*)d_in[10];
    const float* Wo1   = (const float*)d_in[11];
    const float* bo1   = (const float*)d_in[12];
    const float* Wo2   = (const float*)d_in[13];
    const float* bo2   = (const float*)d_in[14];
    const float* Wrel  = (const float*)d_in[15];
    const float* rpb   = (const float*)d_in[16];
    const float* fx_g  = (const float*)d_in[17];
    const float* fx_b  = (const float*)d_in[18];
    const float* fx_w1 = (const float*)d_in[19];
    const float* fx_b1 = (const float*)d_in[20];
    const float* fx_w2 = (const float*)d_in[21];
    const float* fx_b2 = (const float*)d_in[22];
    const float* fy_g  = (const float*)d_in[23];
    const float* fy_b  = (const float*)d_in[24];
    const float* fy_w1 = (const float*)d_in[25];
    const float* fy_b1 = (const float*)d_in[26];
    const float* fy_w2 = (const float*)d_in[27];
    const float* fy_b2 = (const float*)d_in[28];

    cudaFuncSetAttribute(gemm_bf<128, true>,  cudaFuncAttributeMaxDynamicSharedMemorySize, GemmCfg<128>::SMEM);
    cudaFuncSetAttribute(gemm_bf<128, false>, cudaFuncAttributeMaxDynamicSharedMemorySize, GemmCfg<128>::SMEM);
    cudaFuncSetAttribute(gemm_bf<96, false>,  cudaFuncAttributeMaxDynamicSharedMemorySize, GemmCfg<96>::SMEM);
    cudaFuncSetAttribute(gemm_bf<64, true>,   cudaFuncAttributeMaxDynamicSharedMemorySize, GemmCfg<64>::SMEM);
    cudaFuncSetAttribute(gemm_bf<64, false>,  cudaFuncAttributeMaxDynamicSharedMemorySize, GemmCfg<64>::SMEM);
    cudaFuncSetAttribute(softmax2_k, cudaFuncAttributeMaxDynamicSharedMemorySize, SMXSM);

    float* S = nullptr;
    cudaGetSymbolAddress((void**)&S, g_scratch);
    __nv_bfloat16* BF = nullptr;
    cudaGetSymbolAddress((void**)&BF, g_bf);

    float* gy   = S + OFF_Y;
    float* gy1  = S + OFF_Y1;
    float* gk   = S + OFF_K;
    float* gv1  = S + OFF_V1;
    float* gv2  = S + OFF_V2;
    float* grel = S + OFF_REL;
    float* gatt = S + OFF_ATT;
    float* gx4  = S + OFF_X4;
    float* gy4  = S + OFF_Y4;
    (void)gy1;

    #define PLH(off) (BF + (off))
    #define PLL(off, sz) (BF + (off) + (sz))

    float* outx = (float*)d_out;
    float* outy = outx + (long)PB * PN1 * PD;

    dim3 tt(32, 8);

    // ---- ALL weight transpose+splits in ONE launch ----
    {
        WSegs Wg;
        const float* srcs[12] = { W_res, Wq, Wk, Wv2, Wv1, Wo1, Wo2, Wrel,
                                  fx_w1, fx_w2, fy_w1, fy_w2 };
        long ohs[12] = { BF_WRT, BF_WQT, BF_WKT, BF_WV2T, BF_WV1T, BF_WO1T, BF_WO2T, BF_WRELT,
                         BF_FX1T, BF_FX2T, BF_FY1T, BF_FY2T };
        long szs[12] = { SZ_WRT, SZ_WQT, SZ_WKT, SZ_WV2T, SZ_WV1T, SZ_WO1T, SZ_WO2T, SZ_WRELT,
                         SZ_F1, SZ_F2, SZ_F1, SZ_F2 };
        int Ks[12] = { PDY0, PD, PD, PD, PD, HDV, HDV, PNRP, PD, PDFF, PD, PDFF };
        int Ns[12] = { PD, HDK, HDK, HDV, HDV, PD, PD, HDK, PDFF, PD, PDFF, PD };
        for (int i = 0; i < 12; i++) {
            Wg.src[i] = srcs[i];
            Wg.oh[i] = BF + ohs[i];
            Wg.ol[i] = BF + ohs[i] + szs[i];
            Wg.K[i] = Ks[i];
            Wg.N[i] = Ns[i];
        }
        wsplit_all<<<dim3(48, 48, 12), tt>>>(Wg);
    }

    // ---- inputs ----
    ln_k<<<PB * PN1, 256>>>(x, lnx_g, lnx_b, nullptr, PLH(BF_X1), PLL(BF_X1,SZ_X1));
    split_k<<<2048, 256>>>(y0, PLH(BF_Y0), PLL(BF_Y0,SZ_Y0), SZ_Y0);

    // y = y0 @ W_res  (3-pass; BN=64: 192 blocks, 3 CTAs/SM)
    gemm_bf<64,true><<<ngrid(PB*PN2, PD, 64, 1), 256, GemmCfg<64>::SMEM>>>(
        PLH(BF_Y0), PLL(BF_Y0,SZ_Y0), PLH(BF_WRT), PLL(BF_WRT,SZ_WRT),
        nullptr, nullptr, gy, nullptr, nullptr,
        PB*PN2, PD, PDY0, PDY0, PDY0, PD, 0,0,0,0,0,0, 1, 1.f, 0);
    ln_k<<<PB * PN2, 256>>>(gy, lny_g, lny_b, nullptr, PLH(BF_Y1), PLL(BF_Y1,SZ_Y1));

    // q (pre-scaled, planes only; 3-pass), k (3-pass, BN=64), v2 (2-pass, BN=64), v1 (2-pass)
    gemm_bf<128,true><<<ngrid(PB*PN1, HDK, 128, 1), 256, GemmCfg<128>::SMEM>>>(
        PLH(BF_X1), PLL(BF_X1,SZ_X1), PLH(BF_WQT), PLL(BF_WQT,SZ_WQT),
        nullptr, nullptr, nullptr, PLH(BF_Q), PLL(BF_Q,SZ_Q),
        PB*PN1, HDK, PD, PD, PD, HDK, 0,0,0,0,0,0, 1, PSCALE, 0);
    gemm_bf<64,true><<<ngrid(PB*PN2, HDK, 64, 1), 256, GemmCfg<64>::SMEM>>>(
        PLH(BF_Y1), PLL(BF_Y1,SZ_Y1), PLH(BF_WKT), PLL(BF_WKT,SZ_WKT),
        nullptr, nullptr, gk, PLH(BF_K), PLL(BF_K,SZ_K),
        PB*PN2, HDK, PD, PD, PD, HDK, 0,0,0,0,0,0, 1, 1.f, 0);
    gemm_bf<64,false><<<ngrid(PB*PN2, HDV, 64, 1), 256, GemmCfg<64>::SMEM>>>(
        PLH(BF_Y1), nullptr, PLH(BF_WV2T), PLL(BF_WV2T,SZ_WV2T),
        nullptr, nullptr, gv2, nullptr, nullptr,
        PB*PN2, HDV, PD, PD, PD, HDV, 0,0,0,0,0,0, 1, 1.f, 0);
    gemm_bf<128,false><<<ngrid(PB*PN1, HDV, 128, 1), 256, GemmCfg<128>::SMEM>>>(
        PLH(BF_X1), nullptr, PLH(BF_WV1T), PLL(BF_WV1T,SZ_WV1T),
        nullptr, nullptr, gv1, nullptr, nullptr,
        PB*PN1, HDV, PD, PD, PD, HDV, 0,0,0,0,0,0, 1, 1.f, 0);

    // v2T / v1T planes per (b,h)
    tsplit_k<<<dim3(PDV/32, PN2/32, PB*PH), tt>>>(
        gv2, PLH(BF_V2T), PLL(BF_V2T,SZ_V2T), PN2, PDV, HDV,
        (long)PN2*HDV, (long)PDV, (long)PDV*PN2, PH);
    tsplit_k<<<dim3(PDV/32, PN1/32, PB*PH), tt>>>(
        gv1, PLH(BF_V1T), PLL(BF_V1T,SZ_V1T), PN1, PDV, HDV,
        (long)PN1*HDV, (long)PDV, (long)PDV*PN1, PH);

    // pos features + rel_q (planes only; 3-pass; BN=64: 160 blocks)
    pos_k<<<(PMQ + 127) / 128, 128>>>(PLH(BF_POS), PLL(BF_POS,SZ_POS));
    gemm_bf<64,true><<<ngrid(PMQ, HDK, 64, 1), 256, GemmCfg<64>::SMEM>>>(
        PLH(BF_POS), PLL(BF_POS,SZ_POS), PLH(BF_WRELT), PLL(BF_WRELT,SZ_WRELT),
        nullptr, nullptr, nullptr, PLH(BF_RQ), PLL(BF_RQ,SZ_RQ),
        PMQ, HDK, PNRP, PNRP, PNRP, HDK, 0,0,0,0,0,0, 1, 1.f, 0);

    // kb single plane
    kb_k<<<2048, 256>>>(gk, rpb, PLH(BF_KB), PB*PN2*HDK);

    // content = q_scaled @ k^T  (3-pass)
    gemm_bf<128,true><<<ngrid(PN1, PN2, 128, PB*PH), 256, GemmCfg<128>::SMEM>>>(
        PLH(BF_Q), PLL(BF_Q,SZ_Q), PLH(BF_K), PLL(BF_K,SZ_K),
        nullptr, nullptr, gatt, nullptr, nullptr,
        PN1, PN2, PDK, HDK, HDK, PN2,
        (long)PN1*HDK, (long)PDK, (long)PN2*HDK, (long)PDK,
        (long)PH*PN1*PN2, (long)PN1*PN2, PH, 1.f, 0);

    // rel = kb @ rel_q^T  (2-pass: kb single plane)
    gemm_bf<128,false><<<ngrid(PN2, PMQ, 128, PB*PH), 256, GemmCfg<128>::SMEM>>>(
        PLH(BF_KB), nullptr, PLH(BF_RQ), PLL(BF_RQ,SZ_RQ),
        nullptr, nullptr, grel, nullptr, nullptr,
        PN2, PMQ, PDK, HDK, HDK, PMQ,
        (long)PN2*HDK, (long)PDK, 0L, (long)PDK,
        (long)PH*PN2*PMQ, (long)PN2*PMQ, PH, 1.f, 0);

    // tiled softmax -> single bf16 plane
    softmax2_k<<<dim3(PN1/32, PB*PH), 256, SMXSM>>>(gatt, grel, PLH(BF_ATT));

    // attT (single plane)
    bt_k<<<dim3(PN2/32, PN1/32, PB*PH), tt>>>(PLH(BF_ATT), PLH(BF_ATTT), PN1, PN2);

    // out1 = attn @ v2  (2-pass; hi-only output; BN=96, 3 CTAs/SM)
    gemm_bf<96,false><<<ngrid(PN1, PDV, 96, PB*PH), 256, GemmCfg<96>::SMEM>>>(
        PLH(BF_ATT), nullptr, PLH(BF_V2T), PLL(BF_V2T,SZ_V2T),
        nullptr, nullptr, nullptr, PLH(BF_GO1), nullptr,
        PN1, PDV, PN2, PN2, PN2, HDV,
        (long)PH*PN1*PN2, (long)PN1*PN2, (long)PH*PDV*PN2, (long)PDV*PN2,
        (long)PN1*HDV, (long)PDV, PH, 1.f, 0);

    // out2 = attn^T @ v1 (2-pass; hi-only output; BN=96, 3 CTAs/SM)
    gemm_bf<96,false><<<ngrid(PN2, PDV, 96, PB*PH), 256, GemmCfg<96>::SMEM>>>(
        PLH(BF_ATTT), nullptr, PLH(BF_V1T), PLL(BF_V1T,SZ_V1T),
        nullptr, nullptr, nullptr, PLH(BF_GO2), nullptr,
        PN2, PDV, PN1, PN1, PN1, HDV,
        (long)PH*PN2*PN1, (long)PN2*PN1, (long)PH*PDV*PN1, (long)PDV*PN1,
        (long)PN2*HDV, (long)PDV, PH, 1.f, 0);

    // x4 = x + out1 @ Wo1 + bo1 ; y4 = y + out2 @ Wo2 + bo2  (2-pass; Wo2 BN=64)
    gemm_bf<128,false><<<ngrid(PB*PN1, PD, 128, 1), 256, GemmCfg<128>::SMEM>>>(
        PLH(BF_GO1), nullptr, PLH(BF_WO1T), PLL(BF_WO1T,SZ_WO1T),
        bo1, x, gx4, nullptr, nullptr,
        PB*PN1, PD, HDV, HDV, HDV, PD, 0,0,0,0,0,0, 1, 1.f, 0);
    gemm_bf<64,false><<<ngrid(PB*PN2, PD, 64, 1), 256, GemmCfg<64>::SMEM>>>(
        PLH(BF_GO2), nullptr, PLH(BF_WO2T), PLL(BF_WO2T,SZ_WO2T),
        bo2, gy, gy4, nullptr, nullptr,
        PB*PN2, PD, HDV, HDV, HDV, PD, 0,0,0,0,0,0, 1, 1.f, 0);

    // FFN x: hidden hi-only, FFN2 2-pass
    ln_k<<<PB * PN1, 256>>>(gx4, fx_g, fx_b, nullptr, PLH(BF_X1), PLL(BF_X1,SZ_X1));
    gemm_bf<128,true><<<ngrid(PB*PN1, PDFF, 128, 1), 256, GemmCfg<128>::SMEM>>>(
        PLH(BF_X1), PLL(BF_X1,SZ_X1), PLH(BF_FX1T), PLL(BF_FX1T,SZ_F1),
        fx_b1, nullptr, nullptr, PLH(BF_GH), nullptr,
        PB*PN1, PDFF, PD, PD, PD, PDFF, 0,0,0,0,0,0, 1, 1.f, 1);
    gemm_bf<128,false><<<ngrid(PB*PN1, PD, 128, 1), 256, GemmCfg<128>::SMEM>>>(
        PLH(BF_GH), nullptr, PLH(BF_FX2T), PLL(BF_FX2T,SZ_F2),
        fx_b2, gx4, outx, nullptr, nullptr,
        PB*PN1, PD, PDFF, PDFF, PDFF, PD, 0,0,0,0,0,0, 1, 1.f, 0);

    // FFN y: FFN2 BN=64 for fill
    ln_k<<<PB * PN2, 256>>>(gy4, fy_g, fy_b, nullptr, PLH(BF_Y1), PLL(BF_Y1,SZ_Y1));
    gemm_bf<128,true><<<ngrid(PB*PN2, PDFF, 128, 1), 256, GemmCfg<128>::SMEM>>>(
        PLH(BF_Y1), PLL(BF_Y1,SZ_Y1), PLH(BF_FY1T), PLL(BF_FY1T,SZ_F1),
        fy_b1, nullptr, nullptr, PLH(BF_GH), nullptr,
        PB*PN2, PDFF, PD, PD, PD, PDFF, 0,0,0,0,0,0, 1, 1.f, 1);
    gemm_bf<64,false><<<ngrid(PB*PN2, PD, 64, 1), 256, GemmCfg<64>::SMEM>>>(
        PLH(BF_GH), nullptr, PLH(BF_FY2T), PLL(BF_FY2T,SZ_F2),
        fy_b2, gy4, outy, nullptr, nullptr,
        PB*PN2, PD, PDFF, PDFF, PDFF, PD, 0,0,0,0,0,0, 1, 1.f, 0);

    (void)in_sizes; (void)n_in; (void)out_size;
}